// round 13
// baseline (speedup 1.0000x reference)
#include <cuda_runtime.h>
#include <mma.h>
#include <cstdint>

using namespace nvcuda;

#define D_MODEL 1024
#define N_HEADS 16
#define DK      64
#define BATCH   2
#define SEQ     2048
#define MTOT    (BATCH*SEQ)
#define QKVLD   (3*D_MODEL)   // 3072

// ------------------------- scratch (no allocs allowed) ----------------------
__device__ float g_xt  [(size_t)MTOT * D_MODEL];           // tf32-rounded x
__device__ float g_wt  [(size_t)4 * D_MODEL * D_MODEL];    // tf32-rounded Wq,Wk,Wv,Wo
__device__ float g_QKV [(size_t)MTOT * QKVLD];             // fused Q|K|V, ld=3072
__device__ float g_O   [(size_t)MTOT * D_MODEL];
__device__ float g_part[(size_t)BATCH * N_HEADS * SEQ * 16]; // per-tile row sums

// ------------------------- helpers ------------------------------------------
__device__ __forceinline__ float tf32r(float x) {
    uint32_t u;
    asm("cvt.rna.tf32.f32 %0, %1;" : "=r"(u) : "f"(x));
    return __uint_as_float(u);
}
__device__ __forceinline__ uint32_t smem_u32(const void* p) {
    uint32_t a;
    asm("{ .reg .u64 t; cvta.to.shared.u64 t, %1; cvt.u32.u64 %0, t; }" : "=r"(a) : "l"(p));
    return a;
}
__device__ __forceinline__ void cp16(uint32_t dst, const void* src) {
    asm volatile("cp.async.cg.shared.global [%0], [%1], 16;" :: "r"(dst), "l"(src));
}
__device__ __forceinline__ void cp_commit() {
    asm volatile("cp.async.commit_group;" ::: "memory");
}
template<int N> __device__ __forceinline__ void cp_wait() {
    asm volatile("cp.async.wait_group %0;" :: "n"(N) : "memory");
}

// ------------------------- generic tf32 WMMA GEMM (QKV / out proj) ----------
#define BK  32
#define LDS 40
#define NST 2

template<int MODE>   // MODE: 0 plain store, 1 tf32-rounded
__global__ void __launch_bounds__(256, 2)
wmma_gemm(const float* __restrict__ A, const float* __restrict__ B, float* __restrict__ C,
          int K, int lda, int ldb, int ldc)
{
    constexpr int AELEM = 128 * LDS;
    constexpr int BELEM = 128 * LDS;

    extern __shared__ float sm[];
    float* sA = sm;
    float* sB = sm + (size_t)NST * AELEM;

    const int tid = threadIdx.x;
    const int wid = tid >> 5;
    const int warp_m = wid & 1;
    const int warp_n = wid >> 1;

    const int m0 = blockIdx.y * 128;
    const int n0 = blockIdx.x * 128;
    const int nch = K >> 5;

    wmma::fragment<wmma::accumulator, 16, 16, 8, float> cf[4][2];
    #pragma unroll
    for (int i = 0; i < 4; i++)
        #pragma unroll
        for (int j = 0; j < 2; j++)
            wmma::fill_fragment(cf[i][j], 0.0f);

    auto load = [&](int s, int c) {
        const int k0 = c * BK;
        uint32_t aB = smem_u32(sA + (size_t)s * AELEM);
        uint32_t bB = smem_u32(sB + (size_t)s * BELEM);
        #pragma unroll
        for (int j = 0; j < 4; j++) {
            int f = tid + j * 256, r = f >> 3, q = f & 7;
            cp16(aB + (uint32_t)(r * LDS + q * 4) * 4,
                 A + (size_t)(m0 + r) * lda + k0 + q * 4);
        }
        #pragma unroll
        for (int j = 0; j < 4; j++) {
            int f = tid + j * 256, r = f >> 3, q = f & 7;
            cp16(bB + (uint32_t)(r * LDS + q * 4) * 4,
                 B + (size_t)(n0 + r) * ldb + k0 + q * 4);
        }
        cp_commit();
    };

    load(0, 0);

    for (int c = 0; c < nch; c++) {
        const int s = c & 1;
        cp_wait<0>();
        __syncthreads();
        if (c + 1 < nch) load((c + 1) & 1, c + 1);

        const float* As = sA + (size_t)s * AELEM + warp_m * 64 * LDS;
        const float* Bs = sB + (size_t)s * BELEM + warp_n * 32 * LDS;
        #pragma unroll
        for (int kc = 0; kc < 4; kc++) {
            wmma::fragment<wmma::matrix_a, 16, 16, 8, wmma::precision::tf32, wmma::row_major> af[4];
            wmma::fragment<wmma::matrix_b, 16, 16, 8, wmma::precision::tf32, wmma::col_major> bf[2];
            #pragma unroll
            for (int i = 0; i < 4; i++)
                wmma::load_matrix_sync(af[i], As + i * 16 * LDS + kc * 8, LDS);
            #pragma unroll
            for (int j = 0; j < 2; j++)
                wmma::load_matrix_sync(bf[j], Bs + j * 16 * LDS + kc * 8, LDS);
            #pragma unroll
            for (int i = 0; i < 4; i++)
                #pragma unroll
                for (int j = 0; j < 2; j++)
                    wmma::mma_sync(cf[i][j], af[i], bf[j], cf[i][j]);
        }
        __syncthreads();
    }

    #pragma unroll
    for (int i = 0; i < 4; i++) {
        #pragma unroll
        for (int j = 0; j < 2; j++) {
            if (MODE == 1) {
                #pragma unroll
                for (int e = 0; e < 8; e++) cf[i][j].x[e] = tf32r(cf[i][j].x[e]);
            }
            float* Cp = C + (size_t)(m0 + warp_m * 64 + i * 16) * ldc
                          + n0 + warp_n * 32 + j * 16;
            wmma::store_matrix_sync(Cp, cf[i][j], ldc, wmma::mem_row_major);
        }
    }
}

// ------------------------- scores + exp + row partial sums -------------------
// grid (16 ntile, 16 qtile, heads-in-group), 256 threads, 3 CTAs/SM.
#define SLD 68
#define ELD 132

__global__ void __launch_bounds__(256, 3)
scores_exp_kernel(const float* __restrict__ QKV, float* __restrict__ E,
                  float* __restrict__ partial, int z0)
{
    extern __shared__ float sm[];          // union: [Q 128*68 | K 128*68] / [E 128*132]
    float* sQ = sm;
    float* sK = sm + 128 * SLD;

    const int tid = threadIdx.x;
    const int wid = tid >> 5;
    const int z = blockIdx.z + z0, b = z >> 4, h = z & 15;
    const int q0 = blockIdx.y * 128;
    const int n0 = blockIdx.x * 128;

    const float* Qb = QKV + (size_t)b * SEQ * QKVLD + h * DK;
    const float* Kb = QKV + (size_t)b * SEQ * QKVLD + D_MODEL + h * DK;

    {
        uint32_t qB = smem_u32(sQ), kB = smem_u32(sK);
        #pragma unroll
        for (int j = 0; j < 8; j++) {
            int f = tid + j * 256, r = f >> 4, c = f & 15;
            cp16(qB + (uint32_t)(r * SLD + c * 4) * 4, Qb + (size_t)(q0 + r) * QKVLD + c * 4);
        }
        #pragma unroll
        for (int j = 0; j < 8; j++) {
            int f = tid + j * 256, r = f >> 4, c = f & 15;
            cp16(kB + (uint32_t)(r * SLD + c * 4) * 4, Kb + (size_t)(n0 + r) * QKVLD + c * 4);
        }
        cp_commit();
        cp_wait<0>();
    }
    __syncthreads();

    const int wm = wid & 1, wn = wid >> 1;
    wmma::fragment<wmma::accumulator, 16, 16, 8, float> acc[4][2];
    #pragma unroll
    for (int i = 0; i < 4; i++)
        #pragma unroll
        for (int j = 0; j < 2; j++)
            wmma::fill_fragment(acc[i][j], 0.0f);

    #pragma unroll
    for (int ks = 0; ks < 8; ks++) {
        wmma::fragment<wmma::matrix_a, 16, 16, 8, wmma::precision::tf32, wmma::row_major> af[4];
        wmma::fragment<wmma::matrix_b, 16, 16, 8, wmma::precision::tf32, wmma::col_major> bf[2];
        #pragma unroll
        for (int i = 0; i < 4; i++)
            wmma::load_matrix_sync(af[i], sQ + (wm * 64 + i * 16) * SLD + ks * 8, SLD);
        #pragma unroll
        for (int j = 0; j < 2; j++)
            wmma::load_matrix_sync(bf[j], sK + (wn * 32 + j * 16) * SLD + ks * 8, SLD);
        #pragma unroll
        for (int i = 0; i < 4; i++)
            #pragma unroll
            for (int j = 0; j < 2; j++)
                wmma::mma_sync(acc[i][j], af[i], bf[j], acc[i][j]);
    }
    __syncthreads();   // smem union: done with Q/K

    #pragma unroll
    for (int i = 0; i < 4; i++)
        #pragma unroll
        for (int j = 0; j < 2; j++) {
            #pragma unroll
            for (int e = 0; e < 8; e++) acc[i][j].x[e] = __expf(acc[i][j].x[e] * 0.125f);
            wmma::store_matrix_sync(sm + (wm * 64 + i * 16) * ELD + wn * 32 + j * 16,
                                    acc[i][j], ELD, wmma::mem_row_major);
        }
    __syncthreads();

    float* Eb = E + (size_t)z * SEQ * SEQ + (size_t)q0 * SEQ + n0;
    #pragma unroll
    for (int j = 0; j < 16; j++) {
        int f = tid + j * 256, rr = f >> 5, c4 = f & 31;
        *reinterpret_cast<float4*>(Eb + (size_t)rr * SEQ + c4 * 4) =
            *reinterpret_cast<const float4*>(sm + rr * ELD + c4 * 4);
    }
    {
        const int r = tid >> 1, hf = tid & 1;
        const float* row = sm + r * ELD + hf * 64;
        float s = 0.f;
        #pragma unroll
        for (int c = 0; c < 64; c += 4)
            s += (row[c] + row[c + 1]) + (row[c + 2] + row[c + 3]);
        s += __shfl_xor_sync(0xFFFFFFFFu, s, 1);
        if (!hf) partial[((size_t)z * SEQ + q0 + r) * 16 + blockIdx.x] = s;
    }
}

// ------------------------- normalize (write P) + P@V -------------------------
// grid (32 qtile, heads-in-group), 256 threads, 3 CTAs/SM. CTA: 64 q rows.
#define PVLD 68

__global__ void __launch_bounds__(256, 3)
pv_kernel(float* __restrict__ E, const float* __restrict__ QKV,
          const float* __restrict__ partial, float* __restrict__ O, int z0)
{
    extern __shared__ float sm[];            // sE[2][64][68] + sV[2][64][68]
    __shared__ float sinv[64];
    float* sE[2] = { sm,                 sm + 64 * PVLD };
    float* sV[2] = { sm + 2 * 64 * PVLD, sm + 3 * 64 * PVLD };

    const int tid = threadIdx.x;
    const int wid = tid >> 5;
    const int z = blockIdx.y + z0, b = z >> 4, h = z & 15;
    const int q0 = blockIdx.x * 64;

    float* Eb = E + (size_t)z * SEQ * SEQ + (size_t)q0 * SEQ;
    const float* Vb = QKV + (size_t)b * SEQ * QKVLD + 2 * D_MODEL + h * DK;

    // inline row inverses (same summation order across rounds)
    if (tid < 64) {
        const float4* p = reinterpret_cast<const float4*>(
            partial + ((size_t)z * SEQ + q0 + tid) * 16);
        float4 a = p[0], b4 = p[1], c = p[2], d = p[3];
        float s = (((a.x + a.y) + (a.z + a.w)) + ((b4.x + b4.y) + (b4.z + b4.w)))
                + (((c.x + c.y) + (c.z + c.w)) + ((d.x + d.y) + (d.z + d.w)));
        sinv[tid] = 1.0f / s;
    }

    auto prefetch = [&](int kt) {
        uint32_t eB = smem_u32(sE[kt & 1]);
        uint32_t vB = smem_u32(sV[kt & 1]);
        #pragma unroll
        for (int j = 0; j < 4; j++) {
            int f = tid + j * 256, r = f >> 4, c4 = f & 15;
            cp16(eB + (uint32_t)(r * PVLD + c4 * 4) * 4,
                 Eb + (size_t)r * SEQ + kt * 64 + c4 * 4);
        }
        #pragma unroll
        for (int j = 0; j < 4; j++) {
            int f = tid + j * 256, r = f >> 4, c4 = f & 15;
            cp16(vB + (uint32_t)(r * PVLD + c4 * 4) * 4,
                 Vb + (size_t)(kt * 64 + r) * QKVLD + c4 * 4);
        }
        cp_commit();
    };
    prefetch(0);
    prefetch(1);

    const int wm = wid & 1, wn = wid >> 1;   // O(64x64): warp tile 32q x 16d
    wmma::fragment<wmma::accumulator, 16, 16, 8, float> acc[2];
    #pragma unroll
    for (int i = 0; i < 2; i++) wmma::fill_fragment(acc[i], 0.f);

    for (int kt = 0; kt < 32; kt++) {
        float* bufE = sE[kt & 1];
        float* bufV = sV[kt & 1];
        if (kt < 31) cp_wait<1>(); else cp_wait<0>();
        __syncthreads();

        // normalize + tf32-round in smem; write final P to gmem (coalesced)
        #pragma unroll
        for (int j = 0; j < 4; j++) {
            int f = tid + j * 256, r = f >> 4, c4 = f & 15;
            float4* sp = reinterpret_cast<float4*>(bufE + r * PVLD + c4 * 4);
            float4 v = *sp;
            const float iv = sinv[r];
            v.x = tf32r(v.x * iv); v.y = tf32r(v.y * iv);
            v.z = tf32r(v.z * iv); v.w = tf32r(v.w * iv);
            *sp = v;
            *reinterpret_cast<float4*>(Eb + (size_t)r * SEQ + kt * 64 + c4 * 4) = v;
        }
        __syncthreads();

        // O += P_chunk @ V_chunk (both operands from smem)
        #pragma unroll
        for (int ks = 0; ks < 8; ks++) {
            wmma::fragment<wmma::matrix_b, 16, 16, 8, wmma::precision::tf32, wmma::row_major> bf;
            wmma::load_matrix_sync(bf, bufV + (ks * 8) * PVLD + wn * 16, PVLD);
            #pragma unroll
            for (int i = 0; i < 2; i++) {
                wmma::fragment<wmma::matrix_a, 16, 16, 8, wmma::precision::tf32, wmma::row_major> af;
                wmma::load_matrix_sync(af, bufE + (wm * 32 + i * 16) * PVLD + ks * 8, PVLD);
                wmma::mma_sync(acc[i], af, bf, acc[i]);
            }
        }
        __syncthreads();
        if (kt + 2 < 32) prefetch(kt + 2);
    }

    #pragma unroll
    for (int i = 0; i < 2; i++) {
        #pragma unroll
        for (int e = 0; e < 8; e++) acc[i].x[e] = tf32r(acc[i].x[e]);
        float* Op = O + (size_t)(b * SEQ + q0 + wm * 32 + i * 16) * D_MODEL + h * DK + wn * 16;
        wmma::store_matrix_sync(Op, acc[i], D_MODEL, wmma::mem_row_major);
    }
}

// ------------------------- cvt kernels ---------------------------------------
__global__ void cvt_x_kernel(const float4* __restrict__ src, float4* __restrict__ dst, int n4)
{
    int i = blockIdx.x * blockDim.x + threadIdx.x;
    if (i < n4) {
        float4 v = src[i];
        v.x = tf32r(v.x); v.y = tf32r(v.y); v.z = tf32r(v.z); v.w = tf32r(v.w);
        dst[i] = v;
    }
}
__global__ void cvt_w_kernel(const float4* __restrict__ w0, const float4* __restrict__ w1,
                             const float4* __restrict__ w2, const float4* __restrict__ w3,
                             float4* __restrict__ dst)
{
    const int per = D_MODEL * D_MODEL / 4;
    int i = blockIdx.x * blockDim.x + threadIdx.x;
    const float4* src = (i < per) ? w0 : (i < 2 * per) ? w1 : (i < 3 * per) ? w2 : w3;
    float4 v = src[i & (per - 1)];
    v.x = tf32r(v.x); v.y = tf32r(v.y); v.z = tf32r(v.z); v.w = tf32r(v.w);
    dst[i] = v;
}

// ------------------------- host ----------------------------------------------
#define NGROUP 16
#define ZPG    (32 / NGROUP)   // heads per group = 2

extern "C" void kernel_launch(void* const* d_in, const int* in_sizes, int n_in,
                              void* d_out, int out_size)
{
    const float* x  = (const float*)d_in[0];
    const float* Wq = (const float*)d_in[1];
    const float* Wk = (const float*)d_in[2];
    const float* Wv = (const float*)d_in[3];
    const float* Wo = (const float*)d_in[4];
    float* out = (float*)d_out;

    // lazily created once (first call = uncaptured correctness run)
    static cudaStream_t sB = nullptr;
    static cudaEvent_t evS[NGROUP], evB;
    if (sB == nullptr) {
        cudaStreamCreateWithFlags(&sB, cudaStreamNonBlocking);
        for (int g = 0; g < NGROUP; g++)
            cudaEventCreateWithFlags(&evS[g], cudaEventDisableTiming);
        cudaEventCreateWithFlags(&evB, cudaEventDisableTiming);
    }

    float *pxt, *pwt, *pQKV, *pO, *ppart;
    cudaGetSymbolAddress((void**)&pxt,   g_xt);
    cudaGetSymbolAddress((void**)&pwt,   g_wt);
    cudaGetSymbolAddress((void**)&pQKV,  g_QKV);
    cudaGetSymbolAddress((void**)&pO,    g_O);
    cudaGetSymbolAddress((void**)&ppart, g_part);

    const size_t projN = (size_t)MTOT * D_MODEL;
    float* S = out + projN;   // attn_weights region (E -> P in place)
    const size_t M2 = (size_t)D_MODEL * D_MODEL;

    const int smemG  = NST * (128 + 128) * LDS * 4;          //  81920 (proj GEMMs)
    const int smemSC = 2 * 128 * SLD * 4;                    //  69632 (scores union)
    const int smemPV = 4 * 64 * PVLD * 4;                    //  69632 (pv)
    cudaFuncSetAttribute(wmma_gemm<1>,      cudaFuncAttributeMaxDynamicSharedMemorySize, smemG);
    cudaFuncSetAttribute(wmma_gemm<0>,      cudaFuncAttributeMaxDynamicSharedMemorySize, smemG);
    cudaFuncSetAttribute(scores_exp_kernel, cudaFuncAttributeMaxDynamicSharedMemorySize, smemSC);
    cudaFuncSetAttribute(pv_kernel,         cudaFuncAttributeMaxDynamicSharedMemorySize, smemPV);

    // 1) tf32-round inputs
    cvt_x_kernel<<<(int)(projN / 4 / 256), 256>>>((const float4*)x, (float4*)pxt, (int)(projN / 4));
    cvt_w_kernel<<<(int)(4 * M2 / 4 / 256), 256>>>((const float4*)Wq, (const float4*)Wk,
                                                   (const float4*)Wv, (const float4*)Wo, (float4*)pwt);

    // 2) fused QKV projection (tf32-rounded store)
    dim3 gqkv(QKVLD / 128, MTOT / 128);
    wmma_gemm<1><<<gqkv, 256, smemG>>>(pxt, pwt, pQKV, D_MODEL, D_MODEL, D_MODEL, QKVLD);

    // 3) attention: 16 groups of 2 heads; per-group E chunk (8.4MB) stays
    //    L2-hot so pv(g) consumes it while scores(g+1) runs concurrently.
    for (int g = 0; g < NGROUP; g++) {
        scores_exp_kernel<<<dim3(16, 16, ZPG), 256, smemSC>>>(pQKV, S, ppart, ZPG * g);
        cudaEventRecord(evS[g], 0);
        cudaStreamWaitEvent(sB, evS[g], 0);
        pv_kernel<<<dim3(SEQ / 64, ZPG), 256, smemPV, sB>>>(S, pQKV, ppart, pO, ZPG * g);
    }
    cudaEventRecord(evB, sB);
    cudaStreamWaitEvent(0, evB, 0);

    // 4) out = O @ Wo^T
    dim3 gproj(D_MODEL / 128, MTOT / 128);
    wmma_gemm<0><<<gproj, 256, smemG>>>(pO, pwt + 3 * M2, out, D_MODEL, D_MODEL, D_MODEL, D_MODEL);
}

// round 14
// speedup vs baseline: 1.6101x; 1.6101x over previous
#include <cuda_runtime.h>
#include <mma.h>
#include <cstdint>

using namespace nvcuda;

#define D_MODEL 1024
#define N_HEADS 16
#define DK      64
#define BATCH   2
#define SEQ     2048
#define MTOT    (BATCH*SEQ)
#define QKVLD   (3*D_MODEL)   // 3072

// ------------------------- scratch (no allocs allowed) ----------------------
__device__ float g_xt  [(size_t)MTOT * D_MODEL];           // tf32-rounded x
__device__ float g_wt  [(size_t)4 * D_MODEL * D_MODEL];    // tf32-rounded Wq,Wk,Wv,Wo
__device__ float g_QKV [(size_t)MTOT * QKVLD];             // fused Q|K|V, ld=3072
__device__ float g_O   [(size_t)MTOT * D_MODEL];
__device__ float g_part[(size_t)BATCH * N_HEADS * SEQ * 16]; // per-tile row sums

// ------------------------- helpers ------------------------------------------
__device__ __forceinline__ float tf32r(float x) {
    uint32_t u;
    asm("cvt.rna.tf32.f32 %0, %1;" : "=r"(u) : "f"(x));
    return __uint_as_float(u);
}
__device__ __forceinline__ uint32_t smem_u32(const void* p) {
    uint32_t a;
    asm("{ .reg .u64 t; cvta.to.shared.u64 t, %1; cvt.u32.u64 %0, t; }" : "=r"(a) : "l"(p));
    return a;
}
__device__ __forceinline__ void cp16(uint32_t dst, const void* src) {
    asm volatile("cp.async.cg.shared.global [%0], [%1], 16;" :: "r"(dst), "l"(src));
}
__device__ __forceinline__ void cp_commit() {
    asm volatile("cp.async.commit_group;" ::: "memory");
}
template<int N> __device__ __forceinline__ void cp_wait() {
    asm volatile("cp.async.wait_group %0;" :: "n"(N) : "memory");
}

// ------------------------- generic tf32 WMMA GEMM (QKV / out proj) ----------
#define BK  32
#define LDS 40
#define NST 2

template<int MODE>   // MODE: 0 plain store, 1 tf32-rounded
__global__ void __launch_bounds__(256, 2)
wmma_gemm(const float* __restrict__ A, const float* __restrict__ B, float* __restrict__ C,
          int K, int lda, int ldb, int ldc)
{
    constexpr int AELEM = 128 * LDS;
    constexpr int BELEM = 128 * LDS;

    extern __shared__ float sm[];
    float* sA = sm;
    float* sB = sm + (size_t)NST * AELEM;

    const int tid = threadIdx.x;
    const int wid = tid >> 5;
    const int warp_m = wid & 1;
    const int warp_n = wid >> 1;

    const int m0 = blockIdx.y * 128;
    const int n0 = blockIdx.x * 128;
    const int nch = K >> 5;

    wmma::fragment<wmma::accumulator, 16, 16, 8, float> cf[4][2];
    #pragma unroll
    for (int i = 0; i < 4; i++)
        #pragma unroll
        for (int j = 0; j < 2; j++)
            wmma::fill_fragment(cf[i][j], 0.0f);

    auto load = [&](int s, int c) {
        const int k0 = c * BK;
        uint32_t aB = smem_u32(sA + (size_t)s * AELEM);
        uint32_t bB = smem_u32(sB + (size_t)s * BELEM);
        #pragma unroll
        for (int j = 0; j < 4; j++) {
            int f = tid + j * 256, r = f >> 3, q = f & 7;
            cp16(aB + (uint32_t)(r * LDS + q * 4) * 4,
                 A + (size_t)(m0 + r) * lda + k0 + q * 4);
        }
        #pragma unroll
        for (int j = 0; j < 4; j++) {
            int f = tid + j * 256, r = f >> 3, q = f & 7;
            cp16(bB + (uint32_t)(r * LDS + q * 4) * 4,
                 B + (size_t)(n0 + r) * ldb + k0 + q * 4);
        }
        cp_commit();
    };

    load(0, 0);

    for (int c = 0; c < nch; c++) {
        const int s = c & 1;
        cp_wait<0>();
        __syncthreads();
        if (c + 1 < nch) load((c + 1) & 1, c + 1);

        const float* As = sA + (size_t)s * AELEM + warp_m * 64 * LDS;
        const float* Bs = sB + (size_t)s * BELEM + warp_n * 32 * LDS;
        #pragma unroll
        for (int kc = 0; kc < 4; kc++) {
            wmma::fragment<wmma::matrix_a, 16, 16, 8, wmma::precision::tf32, wmma::row_major> af[4];
            wmma::fragment<wmma::matrix_b, 16, 16, 8, wmma::precision::tf32, wmma::col_major> bf[2];
            #pragma unroll
            for (int i = 0; i < 4; i++)
                wmma::load_matrix_sync(af[i], As + i * 16 * LDS + kc * 8, LDS);
            #pragma unroll
            for (int j = 0; j < 2; j++)
                wmma::load_matrix_sync(bf[j], Bs + j * 16 * LDS + kc * 8, LDS);
            #pragma unroll
            for (int i = 0; i < 4; i++)
                #pragma unroll
                for (int j = 0; j < 2; j++)
                    wmma::mma_sync(cf[i][j], af[i], bf[j], cf[i][j]);
        }
        __syncthreads();
    }

    #pragma unroll
    for (int i = 0; i < 4; i++) {
        #pragma unroll
        for (int j = 0; j < 2; j++) {
            if (MODE == 1) {
                #pragma unroll
                for (int e = 0; e < 8; e++) cf[i][j].x[e] = tf32r(cf[i][j].x[e]);
            }
            float* Cp = C + (size_t)(m0 + warp_m * 64 + i * 16) * ldc
                          + n0 + warp_n * 32 + j * 16;
            wmma::store_matrix_sync(Cp, cf[i][j], ldc, wmma::mem_row_major);
        }
    }
}

// ------------------------- scores + exp + row partial sums -------------------
// 64q x 128n tiles: grid (16 ntile, 32 qtile, 32 z), 256 threads, 4 CTAs/SM.
#define SLD 68
#define ELD 132

__global__ void __launch_bounds__(256, 4)
scores_exp_kernel(const float* __restrict__ QKV, float* __restrict__ E,
                  float* __restrict__ partial)
{
    extern __shared__ float sm[];          // union: [Q 64*68 | K 128*68] / [E 64*132]
    float* sQ = sm;
    float* sK = sm + 64 * SLD;

    const int tid = threadIdx.x;
    const int wid = tid >> 5;
    const int z = blockIdx.z, b = z >> 4, h = z & 15;
    const int q0 = blockIdx.y * 64;
    const int n0 = blockIdx.x * 128;

    const float* Qb = QKV + (size_t)b * SEQ * QKVLD + h * DK;
    const float* Kb = QKV + (size_t)b * SEQ * QKVLD + D_MODEL + h * DK;

    {
        uint32_t qB = smem_u32(sQ), kB = smem_u32(sK);
        #pragma unroll
        for (int j = 0; j < 4; j++) {
            int f = tid + j * 256, r = f >> 4, c = f & 15;
            cp16(qB + (uint32_t)(r * SLD + c * 4) * 4, Qb + (size_t)(q0 + r) * QKVLD + c * 4);
        }
        #pragma unroll
        for (int j = 0; j < 8; j++) {
            int f = tid + j * 256, r = f >> 4, c = f & 15;
            cp16(kB + (uint32_t)(r * SLD + c * 4) * 4, Kb + (size_t)(n0 + r) * QKVLD + c * 4);
        }
        cp_commit();
        cp_wait<0>();
    }
    __syncthreads();

    // 8 warps: 2(m) x 4(n); warp tile 32q x 32n
    const int wm = wid & 1, wn = wid >> 1;
    wmma::fragment<wmma::accumulator, 16, 16, 8, float> acc[2][2];
    #pragma unroll
    for (int i = 0; i < 2; i++)
        #pragma unroll
        for (int j = 0; j < 2; j++)
            wmma::fill_fragment(acc[i][j], 0.0f);

    #pragma unroll
    for (int ks = 0; ks < 8; ks++) {
        wmma::fragment<wmma::matrix_a, 16, 16, 8, wmma::precision::tf32, wmma::row_major> af[2];
        wmma::fragment<wmma::matrix_b, 16, 16, 8, wmma::precision::tf32, wmma::col_major> bf[2];
        #pragma unroll
        for (int i = 0; i < 2; i++)
            wmma::load_matrix_sync(af[i], sQ + (wm * 32 + i * 16) * SLD + ks * 8, SLD);
        #pragma unroll
        for (int j = 0; j < 2; j++)
            wmma::load_matrix_sync(bf[j], sK + (wn * 32 + j * 16) * SLD + ks * 8, SLD);
        #pragma unroll
        for (int i = 0; i < 2; i++)
            #pragma unroll
            for (int j = 0; j < 2; j++)
                wmma::mma_sync(acc[i][j], af[i], bf[j], acc[i][j]);
    }
    __syncthreads();   // smem union: done with Q/K

    #pragma unroll
    for (int i = 0; i < 2; i++)
        #pragma unroll
        for (int j = 0; j < 2; j++) {
            #pragma unroll
            for (int e = 0; e < 8; e++) acc[i][j].x[e] = __expf(acc[i][j].x[e] * 0.125f);
            wmma::store_matrix_sync(sm + (wm * 32 + i * 16) * ELD + wn * 32 + j * 16,
                                    acc[i][j], ELD, wmma::mem_row_major);
        }
    __syncthreads();

    // coalesced gmem write (64 x 128) + per-row partial sums
    float* Eb = E + (size_t)z * SEQ * SEQ + (size_t)q0 * SEQ + n0;
    #pragma unroll
    for (int j = 0; j < 8; j++) {
        int f = tid + j * 256, rr = f >> 5, c4 = f & 31;
        *reinterpret_cast<float4*>(Eb + (size_t)rr * SEQ + c4 * 4) =
            *reinterpret_cast<const float4*>(sm + rr * ELD + c4 * 4);
    }
    {
        const int r = tid >> 2, seg = tid & 3;   // 4 threads/row, 32 cols each
        const float* row = sm + r * ELD + seg * 32;
        float s = 0.f;
        #pragma unroll
        for (int c = 0; c < 32; c += 4)
            s += (row[c] + row[c + 1]) + (row[c + 2] + row[c + 3]);
        s += __shfl_xor_sync(0xFFFFFFFFu, s, 1);
        s += __shfl_xor_sync(0xFFFFFFFFu, s, 2);
        if (seg == 0) partial[((size_t)z * SEQ + q0 + r) * 16 + blockIdx.x] = s;
    }
}

// ------------------------- normalize (write P) + P@V -------------------------
// grid (32 qtile, 32 z), 256 threads, 3 CTAs/SM. CTA: 64 q rows.
// Row inverses computed inline from partial (disjoint rows per CTA).
#define PVLD 68

__global__ void __launch_bounds__(256, 3)
pv_kernel(float* __restrict__ E, const float* __restrict__ QKV,
          const float* __restrict__ partial, float* __restrict__ O)
{
    extern __shared__ float sm[];            // sE[2][64][68] + sV[2][64][68]
    __shared__ float sinv[64];
    float* sE[2] = { sm,                 sm + 64 * PVLD };
    float* sV[2] = { sm + 2 * 64 * PVLD, sm + 3 * 64 * PVLD };

    const int tid = threadIdx.x;
    const int wid = tid >> 5;
    const int z = blockIdx.y, b = z >> 4, h = z & 15;
    const int q0 = blockIdx.x * 64;

    float* Eb = E + (size_t)z * SEQ * SEQ + (size_t)q0 * SEQ;
    const float* Vb = QKV + (size_t)b * SEQ * QKVLD + 2 * D_MODEL + h * DK;

    if (tid < 64) {
        const float4* p = reinterpret_cast<const float4*>(
            partial + ((size_t)z * SEQ + q0 + tid) * 16);
        float4 a = p[0], b4 = p[1], c = p[2], d = p[3];
        float s = (((a.x + a.y) + (a.z + a.w)) + ((b4.x + b4.y) + (b4.z + b4.w)))
                + (((c.x + c.y) + (c.z + c.w)) + ((d.x + d.y) + (d.z + d.w)));
        sinv[tid] = 1.0f / s;
    }

    auto prefetch = [&](int kt) {
        uint32_t eB = smem_u32(sE[kt & 1]);
        uint32_t vB = smem_u32(sV[kt & 1]);
        #pragma unroll
        for (int j = 0; j < 4; j++) {
            int f = tid + j * 256, r = f >> 4, c4 = f & 15;
            cp16(eB + (uint32_t)(r * PVLD + c4 * 4) * 4,
                 Eb + (size_t)r * SEQ + kt * 64 + c4 * 4);
        }
        #pragma unroll
        for (int j = 0; j < 4; j++) {
            int f = tid + j * 256, r = f >> 4, c4 = f & 15;
            cp16(vB + (uint32_t)(r * PVLD + c4 * 4) * 4,
                 Vb + (size_t)(kt * 64 + r) * QKVLD + c4 * 4);
        }
        cp_commit();
    };
    prefetch(0);
    prefetch(1);

    const int wm = wid & 1, wn = wid >> 1;   // O(64x64): warp tile 32q x 16d
    wmma::fragment<wmma::accumulator, 16, 16, 8, float> acc[2];
    #pragma unroll
    for (int i = 0; i < 2; i++) wmma::fill_fragment(acc[i], 0.f);

    for (int kt = 0; kt < 32; kt++) {
        float* bufE = sE[kt & 1];
        float* bufV = sV[kt & 1];
        if (kt < 31) cp_wait<1>(); else cp_wait<0>();
        __syncthreads();

        // normalize + tf32-round in smem; write final P to gmem (coalesced)
        #pragma unroll
        for (int j = 0; j < 4; j++) {
            int f = tid + j * 256, r = f >> 4, c4 = f & 15;
            float4* sp = reinterpret_cast<float4*>(bufE + r * PVLD + c4 * 4);
            float4 v = *sp;
            const float iv = sinv[r];
            v.x = tf32r(v.x * iv); v.y = tf32r(v.y * iv);
            v.z = tf32r(v.z * iv); v.w = tf32r(v.w * iv);
            *sp = v;
            *reinterpret_cast<float4*>(Eb + (size_t)r * SEQ + kt * 64 + c4 * 4) = v;
        }
        __syncthreads();

        // O += P_chunk @ V_chunk (both operands from smem)
        #pragma unroll
        for (int ks = 0; ks < 8; ks++) {
            wmma::fragment<wmma::matrix_b, 16, 16, 8, wmma::precision::tf32, wmma::row_major> bf;
            wmma::load_matrix_sync(bf, bufV + (ks * 8) * PVLD + wn * 16, PVLD);
            #pragma unroll
            for (int i = 0; i < 2; i++) {
                wmma::fragment<wmma::matrix_a, 16, 16, 8, wmma::precision::tf32, wmma::row_major> af;
                wmma::load_matrix_sync(af, bufE + (wm * 32 + i * 16) * PVLD + ks * 8, PVLD);
                wmma::mma_sync(acc[i], af, bf, acc[i]);
            }
        }
        __syncthreads();
        if (kt + 2 < 32) prefetch(kt + 2);
    }

    #pragma unroll
    for (int i = 0; i < 2; i++) {
        #pragma unroll
        for (int e = 0; e < 8; e++) acc[i].x[e] = tf32r(acc[i].x[e]);
        float* Op = O + (size_t)(b * SEQ + q0 + wm * 32 + i * 16) * D_MODEL + h * DK + wn * 16;
        wmma::store_matrix_sync(Op, acc[i], D_MODEL, wmma::mem_row_major);
    }
}

// ------------------------- cvt kernels ---------------------------------------
__global__ void cvt_x_kernel(const float4* __restrict__ src, float4* __restrict__ dst, int n4)
{
    int i = blockIdx.x * blockDim.x + threadIdx.x;
    if (i < n4) {
        float4 v = src[i];
        v.x = tf32r(v.x); v.y = tf32r(v.y); v.z = tf32r(v.z); v.w = tf32r(v.w);
        dst[i] = v;
    }
}
__global__ void cvt_w_kernel(const float4* __restrict__ w0, const float4* __restrict__ w1,
                             const float4* __restrict__ w2, const float4* __restrict__ w3,
                             float4* __restrict__ dst)
{
    const int per = D_MODEL * D_MODEL / 4;
    int i = blockIdx.x * blockDim.x + threadIdx.x;
    const float4* src = (i < per) ? w0 : (i < 2 * per) ? w1 : (i < 3 * per) ? w2 : w3;
    float4 v = src[i & (per - 1)];
    v.x = tf32r(v.x); v.y = tf32r(v.y); v.z = tf32r(v.z); v.w = tf32r(v.w);
    dst[i] = v;
}

// ------------------------- host ----------------------------------------------
extern "C" void kernel_launch(void* const* d_in, const int* in_sizes, int n_in,
                              void* d_out, int out_size)
{
    const float* x  = (const float*)d_in[0];
    const float* Wq = (const float*)d_in[1];
    const float* Wk = (const float*)d_in[2];
    const float* Wv = (const float*)d_in[3];
    const float* Wo = (const float*)d_in[4];
    float* out = (float*)d_out;

    float *pxt, *pwt, *pQKV, *pO, *ppart;
    cudaGetSymbolAddress((void**)&pxt,   g_xt);
    cudaGetSymbolAddress((void**)&pwt,   g_wt);
    cudaGetSymbolAddress((void**)&pQKV,  g_QKV);
    cudaGetSymbolAddress((void**)&pO,    g_O);
    cudaGetSymbolAddress((void**)&ppart, g_part);

    const size_t projN = (size_t)MTOT * D_MODEL;
    float* S = out + projN;   // attn_weights region (E -> P in place)
    const size_t M2 = (size_t)D_MODEL * D_MODEL;

    const int smemG  = NST * (128 + 128) * LDS * 4;          //  81920 (proj GEMMs)
    const int smemSC = (64 + 128) * SLD * 4;                 //  52224 (scores union)
    const int smemPV = 4 * 64 * PVLD * 4;                    //  69632 (pv)
    cudaFuncSetAttribute(wmma_gemm<1>,      cudaFuncAttributeMaxDynamicSharedMemorySize, smemG);
    cudaFuncSetAttribute(wmma_gemm<0>,      cudaFuncAttributeMaxDynamicSharedMemorySize, smemG);
    cudaFuncSetAttribute(scores_exp_kernel, cudaFuncAttributeMaxDynamicSharedMemorySize, smemSC);
    cudaFuncSetAttribute(pv_kernel,         cudaFuncAttributeMaxDynamicSharedMemorySize, smemPV);

    // 1) tf32-round inputs
    cvt_x_kernel<<<(int)(projN / 4 / 256), 256>>>((const float4*)x, (float4*)pxt, (int)(projN / 4));
    cvt_w_kernel<<<(int)(4 * M2 / 4 / 256), 256>>>((const float4*)Wq, (const float4*)Wk,
                                                   (const float4*)Wv, (const float4*)Wo, (float4*)pwt);

    // 2) fused QKV projection (tf32-rounded store)
    dim3 gqkv(QKVLD / 128, MTOT / 128);
    wmma_gemm<1><<<gqkv, 256, smemG>>>(pxt, pwt, pQKV, D_MODEL, D_MODEL, D_MODEL, QKVLD);

    // 3) E = exp(QK^T/8) + per-tile row sums (64q x 128n tiles, 4 CTAs/SM)
    scores_exp_kernel<<<dim3(16, 32, BATCH * N_HEADS), 256, smemSC>>>(pQKV, S, ppart);

    // 4) normalize (write P in place, inline row inverses) + O = P @ V
    pv_kernel<<<dim3(SEQ / 64, BATCH * N_HEADS), 256, smemPV>>>(S, pQKV, ppart, pO);

    // 5) out = O @ Wo^T
    dim3 gproj(D_MODEL / 128, MTOT / 128);
    wmma_gemm<0><<<gproj, 256, smemG>>>(pO, pwt + 3 * M2, out, D_MODEL, D_MODEL, D_MODEL, D_MODEL);
}

// round 15
// speedup vs baseline: 1.6217x; 1.0072x over previous
#include <cuda_runtime.h>
#include <mma.h>
#include <cstdint>

using namespace nvcuda;

#define D_MODEL 1024
#define N_HEADS 16
#define DK      64
#define BATCH   2
#define SEQ     2048
#define MTOT    (BATCH*SEQ)
#define QKVLD   (3*D_MODEL)   // 3072

// ------------------------- scratch (no allocs allowed) ----------------------
__device__ float g_xt  [(size_t)MTOT * D_MODEL];           // tf32-rounded x
__device__ float g_wt  [(size_t)4 * D_MODEL * D_MODEL];    // tf32-rounded Wq,Wk,Wv,Wo
__device__ float g_QKV [(size_t)MTOT * QKVLD];             // fused Q|K|V, ld=3072
__device__ float g_O   [(size_t)MTOT * D_MODEL];
__device__ float g_part[(size_t)BATCH * N_HEADS * SEQ * 16]; // per-tile row sums

// ------------------------- helpers ------------------------------------------
__device__ __forceinline__ float tf32r(float x) {
    uint32_t u;
    asm("cvt.rna.tf32.f32 %0, %1;" : "=r"(u) : "f"(x));
    return __uint_as_float(u);
}
__device__ __forceinline__ uint32_t smem_u32(const void* p) {
    uint32_t a;
    asm("{ .reg .u64 t; cvta.to.shared.u64 t, %1; cvt.u32.u64 %0, t; }" : "=r"(a) : "l"(p));
    return a;
}
__device__ __forceinline__ void cp16(uint32_t dst, const void* src) {
    asm volatile("cp.async.cg.shared.global [%0], [%1], 16;" :: "r"(dst), "l"(src));
}
__device__ __forceinline__ void cp_commit() {
    asm volatile("cp.async.commit_group;" ::: "memory");
}
template<int N> __device__ __forceinline__ void cp_wait() {
    asm volatile("cp.async.wait_group %0;" :: "n"(N) : "memory");
}

// ------------------------- generic tf32 WMMA GEMM (QKV / out proj) ----------
#define BK  32
#define LDS 40
#define NST 2

template<int MODE>   // MODE: 0 plain store, 1 tf32-rounded
__global__ void __launch_bounds__(256, 2)
wmma_gemm(const float* __restrict__ A, const float* __restrict__ B, float* __restrict__ C,
          int K, int lda, int ldb, int ldc)
{
    constexpr int AELEM = 128 * LDS;
    constexpr int BELEM = 128 * LDS;

    extern __shared__ float sm[];
    float* sA = sm;
    float* sB = sm + (size_t)NST * AELEM;

    const int tid = threadIdx.x;
    const int wid = tid >> 5;
    const int warp_m = wid & 1;
    const int warp_n = wid >> 1;

    const int m0 = blockIdx.y * 128;
    const int n0 = blockIdx.x * 128;
    const int nch = K >> 5;

    wmma::fragment<wmma::accumulator, 16, 16, 8, float> cf[4][2];
    #pragma unroll
    for (int i = 0; i < 4; i++)
        #pragma unroll
        for (int j = 0; j < 2; j++)
            wmma::fill_fragment(cf[i][j], 0.0f);

    auto load = [&](int s, int c) {
        const int k0 = c * BK;
        uint32_t aB = smem_u32(sA + (size_t)s * AELEM);
        uint32_t bB = smem_u32(sB + (size_t)s * BELEM);
        #pragma unroll
        for (int j = 0; j < 4; j++) {
            int f = tid + j * 256, r = f >> 3, q = f & 7;
            cp16(aB + (uint32_t)(r * LDS + q * 4) * 4,
                 A + (size_t)(m0 + r) * lda + k0 + q * 4);
        }
        #pragma unroll
        for (int j = 0; j < 4; j++) {
            int f = tid + j * 256, r = f >> 3, q = f & 7;
            cp16(bB + (uint32_t)(r * LDS + q * 4) * 4,
                 B + (size_t)(n0 + r) * ldb + k0 + q * 4);
        }
        cp_commit();
    };

    load(0, 0);

    for (int c = 0; c < nch; c++) {
        const int s = c & 1;
        cp_wait<0>();
        __syncthreads();
        if (c + 1 < nch) load((c + 1) & 1, c + 1);

        const float* As = sA + (size_t)s * AELEM + warp_m * 64 * LDS;
        const float* Bs = sB + (size_t)s * BELEM + warp_n * 32 * LDS;
        #pragma unroll
        for (int kc = 0; kc < 4; kc++) {
            wmma::fragment<wmma::matrix_a, 16, 16, 8, wmma::precision::tf32, wmma::row_major> af[4];
            wmma::fragment<wmma::matrix_b, 16, 16, 8, wmma::precision::tf32, wmma::col_major> bf[2];
            #pragma unroll
            for (int i = 0; i < 4; i++)
                wmma::load_matrix_sync(af[i], As + i * 16 * LDS + kc * 8, LDS);
            #pragma unroll
            for (int j = 0; j < 2; j++)
                wmma::load_matrix_sync(bf[j], Bs + j * 16 * LDS + kc * 8, LDS);
            #pragma unroll
            for (int i = 0; i < 4; i++)
                #pragma unroll
                for (int j = 0; j < 2; j++)
                    wmma::mma_sync(cf[i][j], af[i], bf[j], cf[i][j]);
        }
        __syncthreads();
    }

    #pragma unroll
    for (int i = 0; i < 4; i++) {
        #pragma unroll
        for (int j = 0; j < 2; j++) {
            if (MODE == 1) {
                #pragma unroll
                for (int e = 0; e < 8; e++) cf[i][j].x[e] = tf32r(cf[i][j].x[e]);
            }
            float* Cp = C + (size_t)(m0 + warp_m * 64 + i * 16) * ldc
                          + n0 + warp_n * 32 + j * 16;
            wmma::store_matrix_sync(Cp, cf[i][j], ldc, wmma::mem_row_major);
        }
    }
}

// ------------------------- scores + exp + row partial sums -------------------
// 64q x 128n tiles: grid (16 ntile, 32 qtile, 32 z), 256 threads, 4 CTAs/SM.
#define SLD 68
#define ELD 132

__global__ void __launch_bounds__(256, 4)
scores_exp_kernel(const float* __restrict__ QKV, float* __restrict__ E,
                  float* __restrict__ partial)
{
    extern __shared__ float sm[];          // union: [Q 64*68 | K 128*68] / [E 64*132]
    float* sQ = sm;
    float* sK = sm + 64 * SLD;

    const int tid = threadIdx.x;
    const int wid = tid >> 5;
    const int z = blockIdx.z, b = z >> 4, h = z & 15;
    const int q0 = blockIdx.y * 64;
    const int n0 = blockIdx.x * 128;

    const float* Qb = QKV + (size_t)b * SEQ * QKVLD + h * DK;
    const float* Kb = QKV + (size_t)b * SEQ * QKVLD + D_MODEL + h * DK;

    {
        uint32_t qB = smem_u32(sQ), kB = smem_u32(sK);
        #pragma unroll
        for (int j = 0; j < 4; j++) {
            int f = tid + j * 256, r = f >> 4, c = f & 15;
            cp16(qB + (uint32_t)(r * SLD + c * 4) * 4, Qb + (size_t)(q0 + r) * QKVLD + c * 4);
        }
        #pragma unroll
        for (int j = 0; j < 8; j++) {
            int f = tid + j * 256, r = f >> 4, c = f & 15;
            cp16(kB + (uint32_t)(r * SLD + c * 4) * 4, Kb + (size_t)(n0 + r) * QKVLD + c * 4);
        }
        cp_commit();
        cp_wait<0>();
    }
    __syncthreads();

    // 8 warps: 2(m) x 4(n); warp tile 32q x 32n
    const int wm = wid & 1, wn = wid >> 1;
    wmma::fragment<wmma::accumulator, 16, 16, 8, float> acc[2][2];
    #pragma unroll
    for (int i = 0; i < 2; i++)
        #pragma unroll
        for (int j = 0; j < 2; j++)
            wmma::fill_fragment(acc[i][j], 0.0f);

    #pragma unroll
    for (int ks = 0; ks < 8; ks++) {
        wmma::fragment<wmma::matrix_a, 16, 16, 8, wmma::precision::tf32, wmma::row_major> af[2];
        wmma::fragment<wmma::matrix_b, 16, 16, 8, wmma::precision::tf32, wmma::col_major> bf[2];
        #pragma unroll
        for (int i = 0; i < 2; i++)
            wmma::load_matrix_sync(af[i], sQ + (wm * 32 + i * 16) * SLD + ks * 8, SLD);
        #pragma unroll
        for (int j = 0; j < 2; j++)
            wmma::load_matrix_sync(bf[j], sK + (wn * 32 + j * 16) * SLD + ks * 8, SLD);
        #pragma unroll
        for (int i = 0; i < 2; i++)
            #pragma unroll
            for (int j = 0; j < 2; j++)
                wmma::mma_sync(acc[i][j], af[i], bf[j], acc[i][j]);
    }
    __syncthreads();   // smem union: done with Q/K

    #pragma unroll
    for (int i = 0; i < 2; i++)
        #pragma unroll
        for (int j = 0; j < 2; j++) {
            #pragma unroll
            for (int e = 0; e < 8; e++) acc[i][j].x[e] = __expf(acc[i][j].x[e] * 0.125f);
            wmma::store_matrix_sync(sm + (wm * 32 + i * 16) * ELD + wn * 32 + j * 16,
                                    acc[i][j], ELD, wmma::mem_row_major);
        }
    __syncthreads();

    // coalesced gmem write (64 x 128) + per-row partial sums
    float* Eb = E + (size_t)z * SEQ * SEQ + (size_t)q0 * SEQ + n0;
    #pragma unroll
    for (int j = 0; j < 8; j++) {
        int f = tid + j * 256, rr = f >> 5, c4 = f & 31;
        *reinterpret_cast<float4*>(Eb + (size_t)rr * SEQ + c4 * 4) =
            *reinterpret_cast<const float4*>(sm + rr * ELD + c4 * 4);
    }
    {
        const int r = tid >> 2, seg = tid & 3;   // 4 threads/row, 32 cols each
        const float* row = sm + r * ELD + seg * 32;
        float s = 0.f;
        #pragma unroll
        for (int c = 0; c < 32; c += 4)
            s += (row[c] + row[c + 1]) + (row[c + 2] + row[c + 3]);
        s += __shfl_xor_sync(0xFFFFFFFFu, s, 1);
        s += __shfl_xor_sync(0xFFFFFFFFu, s, 2);
        if (seg == 0) partial[((size_t)z * SEQ + q0 + r) * 16 + blockIdx.x] = s;
    }
}

// ------------------------- normalize (write P) + P@V -------------------------
// 128q x 64kv chunks: grid (16 qtile, 32 z), 256 threads, 2 CTAs/SM.
// 8 warps = 4(m) x 2(n), warp tile 32q x 32d; acc[2][2] held across 32 chunks.
#define PVLD 68

__global__ void __launch_bounds__(256, 2)
pv_kernel(float* __restrict__ E, const float* __restrict__ QKV,
          const float* __restrict__ partial, float* __restrict__ O)
{
    extern __shared__ float sm[];            // sE[2][128][68] + sV[2][64][68]
    __shared__ float sinv[128];
    float* sE[2] = { sm,                  sm + 128 * PVLD };
    float* sV[2] = { sm + 2 * 128 * PVLD, sm + 2 * 128 * PVLD + 64 * PVLD };

    const int tid = threadIdx.x;
    const int wid = tid >> 5;
    const int z = blockIdx.y, b = z >> 4, h = z & 15;
    const int q0 = blockIdx.x * 128;

    float* Eb = E + (size_t)z * SEQ * SEQ + (size_t)q0 * SEQ;
    const float* Vb = QKV + (size_t)b * SEQ * QKVLD + 2 * D_MODEL + h * DK;

    // inline row inverses (same summation order across rounds)
    if (tid < 128) {
        const float4* p = reinterpret_cast<const float4*>(
            partial + ((size_t)z * SEQ + q0 + tid) * 16);
        float4 a = p[0], b4 = p[1], c = p[2], d = p[3];
        float s = (((a.x + a.y) + (a.z + a.w)) + ((b4.x + b4.y) + (b4.z + b4.w)))
                + (((c.x + c.y) + (c.z + c.w)) + ((d.x + d.y) + (d.z + d.w)));
        sinv[tid] = 1.0f / s;
    }

    auto prefetch = [&](int kt) {
        uint32_t eB = smem_u32(sE[kt & 1]);
        uint32_t vB = smem_u32(sV[kt & 1]);
        #pragma unroll
        for (int j = 0; j < 8; j++) {
            int f = tid + j * 256, r = f >> 4, c4 = f & 15;
            cp16(eB + (uint32_t)(r * PVLD + c4 * 4) * 4,
                 Eb + (size_t)r * SEQ + kt * 64 + c4 * 4);
        }
        #pragma unroll
        for (int j = 0; j < 4; j++) {
            int f = tid + j * 256, r = f >> 4, c4 = f & 15;
            cp16(vB + (uint32_t)(r * PVLD + c4 * 4) * 4,
                 Vb + (size_t)(kt * 64 + r) * QKVLD + c4 * 4);
        }
        cp_commit();
    };
    prefetch(0);
    prefetch(1);

    const int wm = wid & 3, wn = wid >> 2;   // O(128x64): warp tile 32q x 32d
    wmma::fragment<wmma::accumulator, 16, 16, 8, float> acc[2][2];
    #pragma unroll
    for (int i = 0; i < 2; i++)
        #pragma unroll
        for (int j = 0; j < 2; j++)
            wmma::fill_fragment(acc[i][j], 0.f);

    for (int kt = 0; kt < 32; kt++) {
        float* bufE = sE[kt & 1];
        float* bufV = sV[kt & 1];
        if (kt < 31) cp_wait<1>(); else cp_wait<0>();
        __syncthreads();

        // normalize + tf32-round in smem; write final P to gmem (coalesced)
        #pragma unroll
        for (int j = 0; j < 8; j++) {
            int f = tid + j * 256, r = f >> 4, c4 = f & 15;
            float4* sp = reinterpret_cast<float4*>(bufE + r * PVLD + c4 * 4);
            float4 v = *sp;
            const float iv = sinv[r];
            v.x = tf32r(v.x * iv); v.y = tf32r(v.y * iv);
            v.z = tf32r(v.z * iv); v.w = tf32r(v.w * iv);
            *sp = v;
            *reinterpret_cast<float4*>(Eb + (size_t)r * SEQ + kt * 64 + c4 * 4) = v;
        }
        __syncthreads();

        // O += P_chunk @ V_chunk (both operands from smem)
        #pragma unroll
        for (int ks = 0; ks < 8; ks++) {
            wmma::fragment<wmma::matrix_b, 16, 16, 8, wmma::precision::tf32, wmma::row_major> bf[2];
            #pragma unroll
            for (int j = 0; j < 2; j++)
                wmma::load_matrix_sync(bf[j], bufV + (ks * 8) * PVLD + wn * 32 + j * 16, PVLD);
            #pragma unroll
            for (int i = 0; i < 2; i++) {
                wmma::fragment<wmma::matrix_a, 16, 16, 8, wmma::precision::tf32, wmma::row_major> af;
                wmma::load_matrix_sync(af, bufE + (wm * 32 + i * 16) * PVLD + ks * 8, PVLD);
                #pragma unroll
                for (int j = 0; j < 2; j++)
                    wmma::mma_sync(acc[i][j], af, bf[j], acc[i][j]);
            }
        }
        __syncthreads();
        if (kt + 2 < 32) prefetch(kt + 2);
    }

    #pragma unroll
    for (int i = 0; i < 2; i++)
        #pragma unroll
        for (int j = 0; j < 2; j++) {
            #pragma unroll
            for (int e = 0; e < 8; e++) acc[i][j].x[e] = tf32r(acc[i][j].x[e]);
            float* Op = O + (size_t)(b * SEQ + q0 + wm * 32 + i * 16) * D_MODEL
                          + h * DK + wn * 32 + j * 16;
            wmma::store_matrix_sync(Op, acc[i][j], D_MODEL, wmma::mem_row_major);
        }
}

// ------------------------- cvt kernels ---------------------------------------
__global__ void cvt_x_kernel(const float4* __restrict__ src, float4* __restrict__ dst, int n4)
{
    int i = blockIdx.x * blockDim.x + threadIdx.x;
    if (i < n4) {
        float4 v = src[i];
        v.x = tf32r(v.x); v.y = tf32r(v.y); v.z = tf32r(v.z); v.w = tf32r(v.w);
        dst[i] = v;
    }
}
__global__ void cvt_w_kernel(const float4* __restrict__ w0, const float4* __restrict__ w1,
                             const float4* __restrict__ w2, const float4* __restrict__ w3,
                             float4* __restrict__ dst)
{
    const int per = D_MODEL * D_MODEL / 4;
    int i = blockIdx.x * blockDim.x + threadIdx.x;
    const float4* src = (i < per) ? w0 : (i < 2 * per) ? w1 : (i < 3 * per) ? w2 : w3;
    float4 v = src[i & (per - 1)];
    v.x = tf32r(v.x); v.y = tf32r(v.y); v.z = tf32r(v.z); v.w = tf32r(v.w);
    dst[i] = v;
}

// ------------------------- host ----------------------------------------------
extern "C" void kernel_launch(void* const* d_in, const int* in_sizes, int n_in,
                              void* d_out, int out_size)
{
    const float* x  = (const float*)d_in[0];
    const float* Wq = (const float*)d_in[1];
    const float* Wk = (const float*)d_in[2];
    const float* Wv = (const float*)d_in[3];
    const float* Wo = (const float*)d_in[4];
    float* out = (float*)d_out;

    float *pxt, *pwt, *pQKV, *pO, *ppart;
    cudaGetSymbolAddress((void**)&pxt,   g_xt);
    cudaGetSymbolAddress((void**)&pwt,   g_wt);
    cudaGetSymbolAddress((void**)&pQKV,  g_QKV);
    cudaGetSymbolAddress((void**)&pO,    g_O);
    cudaGetSymbolAddress((void**)&ppart, g_part);

    const size_t projN = (size_t)MTOT * D_MODEL;
    float* S = out + projN;   // attn_weights region (E -> P in place)
    const size_t M2 = (size_t)D_MODEL * D_MODEL;

    const int smemG  = NST * (128 + 128) * LDS * 4;          //  81920 (proj GEMMs)
    const int smemSC = (64 + 128) * SLD * 4;                 //  52224 (scores union)
    const int smemPV = (2 * 128 + 2 * 64) * PVLD * 4;        // 104448 (pv)
    cudaFuncSetAttribute(wmma_gemm<1>,      cudaFuncAttributeMaxDynamicSharedMemorySize, smemG);
    cudaFuncSetAttribute(wmma_gemm<0>,      cudaFuncAttributeMaxDynamicSharedMemorySize, smemG);
    cudaFuncSetAttribute(scores_exp_kernel, cudaFuncAttributeMaxDynamicSharedMemorySize, smemSC);
    cudaFuncSetAttribute(pv_kernel,         cudaFuncAttributeMaxDynamicSharedMemorySize, smemPV);

    // 1) tf32-round inputs
    cvt_x_kernel<<<(int)(projN / 4 / 256), 256>>>((const float4*)x, (float4*)pxt, (int)(projN / 4));
    cvt_w_kernel<<<(int)(4 * M2 / 4 / 256), 256>>>((const float4*)Wq, (const float4*)Wk,
                                                   (const float4*)Wv, (const float4*)Wo, (float4*)pwt);

    // 2) fused QKV projection (tf32-rounded store)
    dim3 gqkv(QKVLD / 128, MTOT / 128);
    wmma_gemm<1><<<gqkv, 256, smemG>>>(pxt, pwt, pQKV, D_MODEL, D_MODEL, D_MODEL, QKVLD);

    // 3) E = exp(QK^T/8) + per-tile row sums (64q x 128n tiles, 4 CTAs/SM)
    scores_exp_kernel<<<dim3(16, 32, BATCH * N_HEADS), 256, smemSC>>>(pQKV, S, ppart);

    // 4) normalize (write P in place, inline row inverses) + O = P @ V
    //    128q x 64kv chunks, 2 CTAs/SM
    pv_kernel<<<dim3(SEQ / 128, BATCH * N_HEADS), 256, smemPV>>>(S, pQKV, ppart, pO);

    // 5) out = O @ Wo^T
    dim3 gproj(D_MODEL / 128, MTOT / 128);
    wmma_gemm<0><<<gproj, 256, smemG>>>(pO, pwt + 3 * M2, out, D_MODEL, D_MODEL, D_MODEL, D_MODEL);
}

// round 16
// speedup vs baseline: 1.6262x; 1.0028x over previous
#include <cuda_runtime.h>
#include <mma.h>
#include <cstdint>

using namespace nvcuda;

#define D_MODEL 1024
#define N_HEADS 16
#define DK      64
#define BATCH   2
#define SEQ     2048
#define MTOT    (BATCH*SEQ)
#define QKVLD   (3*D_MODEL)   // 3072

// ------------------------- scratch (no allocs allowed) ----------------------
__device__ float g_xt  [(size_t)MTOT * D_MODEL];           // tf32-rounded x
__device__ float g_wt  [(size_t)4 * D_MODEL * D_MODEL];    // tf32-rounded Wq,Wk,Wv,Wo
__device__ float g_QKV [(size_t)MTOT * QKVLD];             // fused Q|K|V, ld=3072
__device__ float g_O   [(size_t)MTOT * D_MODEL];
__device__ float g_part[(size_t)BATCH * N_HEADS * SEQ * 16]; // per-tile row sums

// ------------------------- helpers ------------------------------------------
__device__ __forceinline__ float tf32r(float x) {
    uint32_t u;
    asm("cvt.rna.tf32.f32 %0, %1;" : "=r"(u) : "f"(x));
    return __uint_as_float(u);
}
// FMA-pipe exp (no MUFU): rel err ~2e-7 for |x| < 30
__device__ __forceinline__ float exp_fma(float x) {
    float n = rintf(x * 1.4426950408889634f);
    float u = fmaf(n, -0.6931471805599453f, x);
    float p = 1.9841270e-4f;
    p = fmaf(p, u, 1.3888889e-3f);
    p = fmaf(p, u, 8.3333333e-3f);
    p = fmaf(p, u, 4.1666667e-2f);
    p = fmaf(p, u, 1.6666667e-1f);
    p = fmaf(p, u, 0.5f);
    p = fmaf(p, u, 1.0f);
    p = fmaf(p, u, 1.0f);
    return p * __int_as_float(((int)n + 127) << 23);
}
__device__ __forceinline__ uint32_t smem_u32(const void* p) {
    uint32_t a;
    asm("{ .reg .u64 t; cvta.to.shared.u64 t, %1; cvt.u32.u64 %0, t; }" : "=r"(a) : "l"(p));
    return a;
}
__device__ __forceinline__ void cp16(uint32_t dst, const void* src) {
    asm volatile("cp.async.cg.shared.global [%0], [%1], 16;" :: "r"(dst), "l"(src));
}
__device__ __forceinline__ void cp_commit() {
    asm volatile("cp.async.commit_group;" ::: "memory");
}
template<int N> __device__ __forceinline__ void cp_wait() {
    asm volatile("cp.async.wait_group %0;" :: "n"(N) : "memory");
}

// ------------------------- generic tf32 WMMA GEMM (QKV / out proj) ----------
#define BK  32
#define LDS 40
#define NST 2

template<int MODE>   // MODE: 0 plain store, 1 tf32-rounded
__global__ void __launch_bounds__(256, 2)
wmma_gemm(const float* __restrict__ A, const float* __restrict__ B, float* __restrict__ C,
          int K, int lda, int ldb, int ldc)
{
    constexpr int AELEM = 128 * LDS;
    constexpr int BELEM = 128 * LDS;

    extern __shared__ float sm[];
    float* sA = sm;
    float* sB = sm + (size_t)NST * AELEM;

    const int tid = threadIdx.x;
    const int wid = tid >> 5;
    const int warp_m = wid & 1;
    const int warp_n = wid >> 1;

    const int m0 = blockIdx.y * 128;
    const int n0 = blockIdx.x * 128;
    const int nch = K >> 5;

    wmma::fragment<wmma::accumulator, 16, 16, 8, float> cf[4][2];
    #pragma unroll
    for (int i = 0; i < 4; i++)
        #pragma unroll
        for (int j = 0; j < 2; j++)
            wmma::fill_fragment(cf[i][j], 0.0f);

    auto load = [&](int s, int c) {
        const int k0 = c * BK;
        uint32_t aB = smem_u32(sA + (size_t)s * AELEM);
        uint32_t bB = smem_u32(sB + (size_t)s * BELEM);
        #pragma unroll
        for (int j = 0; j < 4; j++) {
            int f = tid + j * 256, r = f >> 3, q = f & 7;
            cp16(aB + (uint32_t)(r * LDS + q * 4) * 4,
                 A + (size_t)(m0 + r) * lda + k0 + q * 4);
        }
        #pragma unroll
        for (int j = 0; j < 4; j++) {
            int f = tid + j * 256, r = f >> 3, q = f & 7;
            cp16(bB + (uint32_t)(r * LDS + q * 4) * 4,
                 B + (size_t)(n0 + r) * ldb + k0 + q * 4);
        }
        cp_commit();
    };

    load(0, 0);

    for (int c = 0; c < nch; c++) {
        const int s = c & 1;
        cp_wait<0>();
        __syncthreads();
        if (c + 1 < nch) load((c + 1) & 1, c + 1);

        const float* As = sA + (size_t)s * AELEM + warp_m * 64 * LDS;
        const float* Bs = sB + (size_t)s * BELEM + warp_n * 32 * LDS;
        #pragma unroll
        for (int kc = 0; kc < 4; kc++) {
            wmma::fragment<wmma::matrix_a, 16, 16, 8, wmma::precision::tf32, wmma::row_major> af[4];
            wmma::fragment<wmma::matrix_b, 16, 16, 8, wmma::precision::tf32, wmma::col_major> bf[2];
            #pragma unroll
            for (int i = 0; i < 4; i++)
                wmma::load_matrix_sync(af[i], As + i * 16 * LDS + kc * 8, LDS);
            #pragma unroll
            for (int j = 0; j < 2; j++)
                wmma::load_matrix_sync(bf[j], Bs + j * 16 * LDS + kc * 8, LDS);
            #pragma unroll
            for (int i = 0; i < 4; i++)
                #pragma unroll
                for (int j = 0; j < 2; j++)
                    wmma::mma_sync(cf[i][j], af[i], bf[j], cf[i][j]);
        }
        __syncthreads();
    }

    #pragma unroll
    for (int i = 0; i < 4; i++) {
        #pragma unroll
        for (int j = 0; j < 2; j++) {
            if (MODE == 1) {
                #pragma unroll
                for (int e = 0; e < 8; e++) cf[i][j].x[e] = tf32r(cf[i][j].x[e]);
            }
            float* Cp = C + (size_t)(m0 + warp_m * 64 + i * 16) * ldc
                          + n0 + warp_n * 32 + j * 16;
            wmma::store_matrix_sync(Cp, cf[i][j], ldc, wmma::mem_row_major);
        }
    }
}

// ------------------------- scores + exp + row partial sums -------------------
// 64q x 128n tiles: grid (16 ntile, 32 qtile, 32 z), 256 threads, 4 CTAs/SM.
// exp split 50/50 between MUFU (__expf) and FMA-pipe polynomial to balance pipes.
#define SLD 68
#define ELD 132

__global__ void __launch_bounds__(256, 4)
scores_exp_kernel(const float* __restrict__ QKV, float* __restrict__ E,
                  float* __restrict__ partial)
{
    extern __shared__ float sm[];          // union: [Q 64*68 | K 128*68] / [E 64*132]
    float* sQ = sm;
    float* sK = sm + 64 * SLD;

    const int tid = threadIdx.x;
    const int wid = tid >> 5;
    const int z = blockIdx.z, b = z >> 4, h = z & 15;
    const int q0 = blockIdx.y * 64;
    const int n0 = blockIdx.x * 128;

    const float* Qb = QKV + (size_t)b * SEQ * QKVLD + h * DK;
    const float* Kb = QKV + (size_t)b * SEQ * QKVLD + D_MODEL + h * DK;

    {
        uint32_t qB = smem_u32(sQ), kB = smem_u32(sK);
        #pragma unroll
        for (int j = 0; j < 4; j++) {
            int f = tid + j * 256, r = f >> 4, c = f & 15;
            cp16(qB + (uint32_t)(r * SLD + c * 4) * 4, Qb + (size_t)(q0 + r) * QKVLD + c * 4);
        }
        #pragma unroll
        for (int j = 0; j < 8; j++) {
            int f = tid + j * 256, r = f >> 4, c = f & 15;
            cp16(kB + (uint32_t)(r * SLD + c * 4) * 4, Kb + (size_t)(n0 + r) * QKVLD + c * 4);
        }
        cp_commit();
        cp_wait<0>();
    }
    __syncthreads();

    // 8 warps: 2(m) x 4(n); warp tile 32q x 32n
    const int wm = wid & 1, wn = wid >> 1;
    wmma::fragment<wmma::accumulator, 16, 16, 8, float> acc[2][2];
    #pragma unroll
    for (int i = 0; i < 2; i++)
        #pragma unroll
        for (int j = 0; j < 2; j++)
            wmma::fill_fragment(acc[i][j], 0.0f);

    #pragma unroll
    for (int ks = 0; ks < 8; ks++) {
        wmma::fragment<wmma::matrix_a, 16, 16, 8, wmma::precision::tf32, wmma::row_major> af[2];
        wmma::fragment<wmma::matrix_b, 16, 16, 8, wmma::precision::tf32, wmma::col_major> bf[2];
        #pragma unroll
        for (int i = 0; i < 2; i++)
            wmma::load_matrix_sync(af[i], sQ + (wm * 32 + i * 16) * SLD + ks * 8, SLD);
        #pragma unroll
        for (int j = 0; j < 2; j++)
            wmma::load_matrix_sync(bf[j], sK + (wn * 32 + j * 16) * SLD + ks * 8, SLD);
        #pragma unroll
        for (int i = 0; i < 2; i++)
            #pragma unroll
            for (int j = 0; j < 2; j++)
                wmma::mma_sync(acc[i][j], af[i], bf[j], acc[i][j]);
    }
    __syncthreads();   // smem union: done with Q/K

    // E = exp(s/8): even elements on MUFU, odd on FMA pipe (pipe balance)
    #pragma unroll
    for (int i = 0; i < 2; i++)
        #pragma unroll
        for (int j = 0; j < 2; j++) {
            #pragma unroll
            for (int e = 0; e < 8; e += 2) {
                acc[i][j].x[e]     = __expf(acc[i][j].x[e] * 0.125f);
                acc[i][j].x[e + 1] = exp_fma(acc[i][j].x[e + 1] * 0.125f);
            }
            wmma::store_matrix_sync(sm + (wm * 32 + i * 16) * ELD + wn * 32 + j * 16,
                                    acc[i][j], ELD, wmma::mem_row_major);
        }
    __syncthreads();

    // coalesced gmem write (64 x 128) + per-row partial sums
    float* Eb = E + (size_t)z * SEQ * SEQ + (size_t)q0 * SEQ + n0;
    #pragma unroll
    for (int j = 0; j < 8; j++) {
        int f = tid + j * 256, rr = f >> 5, c4 = f & 31;
        *reinterpret_cast<float4*>(Eb + (size_t)rr * SEQ + c4 * 4) =
            *reinterpret_cast<const float4*>(sm + rr * ELD + c4 * 4);
    }
    {
        const int r = tid >> 2, seg = tid & 3;   // 4 threads/row, 32 cols each
        const float* row = sm + r * ELD + seg * 32;
        float s = 0.f;
        #pragma unroll
        for (int c = 0; c < 32; c += 4)
            s += (row[c] + row[c + 1]) + (row[c + 2] + row[c + 3]);
        s += __shfl_xor_sync(0xFFFFFFFFu, s, 1);
        s += __shfl_xor_sync(0xFFFFFFFFu, s, 2);
        if (seg == 0) partial[((size_t)z * SEQ + q0 + r) * 16 + blockIdx.x] = s;
    }
}

// ------------------------- normalize (write P) + P@V -------------------------
// 128q x 64kv chunks: grid (16 qtile, 32 z), 256 threads, 2 CTAs/SM.
#define PVLD 68

__global__ void __launch_bounds__(256, 2)
pv_kernel(float* __restrict__ E, const float* __restrict__ QKV,
          const float* __restrict__ partial, float* __restrict__ O)
{
    extern __shared__ float sm[];            // sE[2][128][68] + sV[2][64][68]
    __shared__ float sinv[128];
    float* sE[2] = { sm,                  sm + 128 * PVLD };
    float* sV[2] = { sm + 2 * 128 * PVLD, sm + 2 * 128 * PVLD + 64 * PVLD };

    const int tid = threadIdx.x;
    const int wid = tid >> 5;
    const int z = blockIdx.y, b = z >> 4, h = z & 15;
    const int q0 = blockIdx.x * 128;

    float* Eb = E + (size_t)z * SEQ * SEQ + (size_t)q0 * SEQ;
    const float* Vb = QKV + (size_t)b * SEQ * QKVLD + 2 * D_MODEL + h * DK;

    if (tid < 128) {
        const float4* p = reinterpret_cast<const float4*>(
            partial + ((size_t)z * SEQ + q0 + tid) * 16);
        float4 a = p[0], b4 = p[1], c = p[2], d = p[3];
        float s = (((a.x + a.y) + (a.z + a.w)) + ((b4.x + b4.y) + (b4.z + b4.w)))
                + (((c.x + c.y) + (c.z + c.w)) + ((d.x + d.y) + (d.z + d.w)));
        sinv[tid] = 1.0f / s;
    }

    auto prefetch = [&](int kt) {
        uint32_t eB = smem_u32(sE[kt & 1]);
        uint32_t vB = smem_u32(sV[kt & 1]);
        #pragma unroll
        for (int j = 0; j < 8; j++) {
            int f = tid + j * 256, r = f >> 4, c4 = f & 15;
            cp16(eB + (uint32_t)(r * PVLD + c4 * 4) * 4,
                 Eb + (size_t)r * SEQ + kt * 64 + c4 * 4);
        }
        #pragma unroll
        for (int j = 0; j < 4; j++) {
            int f = tid + j * 256, r = f >> 4, c4 = f & 15;
            cp16(vB + (uint32_t)(r * PVLD + c4 * 4) * 4,
                 Vb + (size_t)(kt * 64 + r) * QKVLD + c4 * 4);
        }
        cp_commit();
    };
    prefetch(0);
    prefetch(1);

    const int wm = wid & 3, wn = wid >> 2;   // O(128x64): warp tile 32q x 32d
    wmma::fragment<wmma::accumulator, 16, 16, 8, float> acc[2][2];
    #pragma unroll
    for (int i = 0; i < 2; i++)
        #pragma unroll
        for (int j = 0; j < 2; j++)
            wmma::fill_fragment(acc[i][j], 0.f);

    for (int kt = 0; kt < 32; kt++) {
        float* bufE = sE[kt & 1];
        float* bufV = sV[kt & 1];
        if (kt < 31) cp_wait<1>(); else cp_wait<0>();
        __syncthreads();

        // normalize + tf32-round in smem; write final P to gmem (coalesced)
        #pragma unroll
        for (int j = 0; j < 8; j++) {
            int f = tid + j * 256, r = f >> 4, c4 = f & 15;
            float4* sp = reinterpret_cast<float4*>(bufE + r * PVLD + c4 * 4);
            float4 v = *sp;
            const float iv = sinv[r];
            v.x = tf32r(v.x * iv); v.y = tf32r(v.y * iv);
            v.z = tf32r(v.z * iv); v.w = tf32r(v.w * iv);
            *sp = v;
            *reinterpret_cast<float4*>(Eb + (size_t)r * SEQ + kt * 64 + c4 * 4) = v;
        }
        __syncthreads();

        // O += P_chunk @ V_chunk (both operands from smem)
        #pragma unroll
        for (int ks = 0; ks < 8; ks++) {
            wmma::fragment<wmma::matrix_b, 16, 16, 8, wmma::precision::tf32, wmma::row_major> bf[2];
            #pragma unroll
            for (int j = 0; j < 2; j++)
                wmma::load_matrix_sync(bf[j], bufV + (ks * 8) * PVLD + wn * 32 + j * 16, PVLD);
            #pragma unroll
            for (int i = 0; i < 2; i++) {
                wmma::fragment<wmma::matrix_a, 16, 16, 8, wmma::precision::tf32, wmma::row_major> af;
                wmma::load_matrix_sync(af, bufE + (wm * 32 + i * 16) * PVLD + ks * 8, PVLD);
                #pragma unroll
                for (int j = 0; j < 2; j++)
                    wmma::mma_sync(acc[i][j], af, bf[j], acc[i][j]);
            }
        }
        __syncthreads();
        if (kt + 2 < 32) prefetch(kt + 2);
    }

    #pragma unroll
    for (int i = 0; i < 2; i++)
        #pragma unroll
        for (int j = 0; j < 2; j++) {
            #pragma unroll
            for (int e = 0; e < 8; e++) acc[i][j].x[e] = tf32r(acc[i][j].x[e]);
            float* Op = O + (size_t)(b * SEQ + q0 + wm * 32 + i * 16) * D_MODEL
                          + h * DK + wn * 32 + j * 16;
            wmma::store_matrix_sync(Op, acc[i][j], D_MODEL, wmma::mem_row_major);
        }
}

// ------------------------- cvt kernels ---------------------------------------
__global__ void cvt_x_kernel(const float4* __restrict__ src, float4* __restrict__ dst, int n4)
{
    int i = blockIdx.x * blockDim.x + threadIdx.x;
    if (i < n4) {
        float4 v = src[i];
        v.x = tf32r(v.x); v.y = tf32r(v.y); v.z = tf32r(v.z); v.w = tf32r(v.w);
        dst[i] = v;
    }
}
__global__ void cvt_w_kernel(const float4* __restrict__ w0, const float4* __restrict__ w1,
                             const float4* __restrict__ w2, const float4* __restrict__ w3,
                             float4* __restrict__ dst)
{
    const int per = D_MODEL * D_MODEL / 4;
    int i = blockIdx.x * blockDim.x + threadIdx.x;
    const float4* src = (i < per) ? w0 : (i < 2 * per) ? w1 : (i < 3 * per) ? w2 : w3;
    float4 v = src[i & (per - 1)];
    v.x = tf32r(v.x); v.y = tf32r(v.y); v.z = tf32r(v.z); v.w = tf32r(v.w);
    dst[i] = v;
}

// ------------------------- host ----------------------------------------------
extern "C" void kernel_launch(void* const* d_in, const int* in_sizes, int n_in,
                              void* d_out, int out_size)
{
    const float* x  = (const float*)d_in[0];
    const float* Wq = (const float*)d_in[1];
    const float* Wk = (const float*)d_in[2];
    const float* Wv = (const float*)d_in[3];
    const float* Wo = (const float*)d_in[4];
    float* out = (float*)d_out;

    float *pxt, *pwt, *pQKV, *pO, *ppart;
    cudaGetSymbolAddress((void**)&pxt,   g_xt);
    cudaGetSymbolAddress((void**)&pwt,   g_wt);
    cudaGetSymbolAddress((void**)&pQKV,  g_QKV);
    cudaGetSymbolAddress((void**)&pO,    g_O);
    cudaGetSymbolAddress((void**)&ppart, g_part);

    const size_t projN = (size_t)MTOT * D_MODEL;
    float* S = out + projN;   // attn_weights region (E -> P in place)
    const size_t M2 = (size_t)D_MODEL * D_MODEL;

    const int smemG  = NST * (128 + 128) * LDS * 4;          //  81920 (proj GEMMs)
    const int smemSC = (64 + 128) * SLD * 4;                 //  52224 (scores union)
    const int smemPV = (2 * 128 + 2 * 64) * PVLD * 4;        // 104448 (pv)
    cudaFuncSetAttribute(wmma_gemm<1>,      cudaFuncAttributeMaxDynamicSharedMemorySize, smemG);
    cudaFuncSetAttribute(wmma_gemm<0>,      cudaFuncAttributeMaxDynamicSharedMemorySize, smemG);
    cudaFuncSetAttribute(scores_exp_kernel, cudaFuncAttributeMaxDynamicSharedMemorySize, smemSC);
    cudaFuncSetAttribute(pv_kernel,         cudaFuncAttributeMaxDynamicSharedMemorySize, smemPV);

    // 1) tf32-round inputs
    cvt_x_kernel<<<(int)(projN / 4 / 256), 256>>>((const float4*)x, (float4*)pxt, (int)(projN / 4));
    cvt_w_kernel<<<(int)(4 * M2 / 4 / 256), 256>>>((const float4*)Wq, (const float4*)Wk,
                                                   (const float4*)Wv, (const float4*)Wo, (float4*)pwt);

    // 2) fused QKV projection (tf32-rounded store)
    dim3 gqkv(QKVLD / 128, MTOT / 128);
    wmma_gemm<1><<<gqkv, 256, smemG>>>(pxt, pwt, pQKV, D_MODEL, D_MODEL, D_MODEL, QKVLD);

    // 3) E = exp(QK^T/8) + per-tile row sums (64q x 128n tiles, 4 CTAs/SM)
    scores_exp_kernel<<<dim3(16, 32, BATCH * N_HEADS), 256, smemSC>>>(pQKV, S, ppart);

    // 4) normalize (write P in place, inline row inverses) + O = P @ V
    pv_kernel<<<dim3(SEQ / 128, BATCH * N_HEADS), 256, smemPV>>>(S, pQKV, ppart, pO);

    // 5) out = O @ Wo^T
    dim3 gproj(D_MODEL / 128, MTOT / 128);
    wmma_gemm<0><<<gproj, 256, smemG>>>(pO, pwt + 3 * M2, out, D_MODEL, D_MODEL, D_MODEL, D_MODEL);
}

// round 17
// speedup vs baseline: 1.6921x; 1.0406x over previous
#include <cuda_runtime.h>
#include <mma.h>
#include <cstdint>

using namespace nvcuda;

#define D_MODEL 1024
#define N_HEADS 16
#define DK      64
#define BATCH   2
#define SEQ     2048
#define MTOT    (BATCH*SEQ)
#define QKVLD   (3*D_MODEL)   // 3072

// ------------------------- scratch (no allocs allowed) ----------------------
__device__ float g_xt    [(size_t)MTOT * D_MODEL];         // tf32-rounded x
__device__ float g_wt    [(size_t)4 * D_MODEL * D_MODEL];  // tf32-rounded Wq,Wk,Wv,Wo
__device__ float g_QKV   [(size_t)MTOT * QKVLD];           // fused Q|K|V, ld=3072
__device__ float g_O     [(size_t)MTOT * D_MODEL];
__device__ float g_rowsum[(size_t)BATCH * N_HEADS * SEQ];  // full row sums of E

// ------------------------- helpers ------------------------------------------
__device__ __forceinline__ float tf32r(float x) {
    uint32_t u;
    asm("cvt.rna.tf32.f32 %0, %1;" : "=r"(u) : "f"(x));
    return __uint_as_float(u);
}
__device__ __forceinline__ uint32_t smem_u32(const void* p) {
    uint32_t a;
    asm("{ .reg .u64 t; cvta.to.shared.u64 t, %1; cvt.u32.u64 %0, t; }" : "=r"(a) : "l"(p));
    return a;
}
__device__ __forceinline__ void cp16(uint32_t dst, const void* src) {
    asm volatile("cp.async.cg.shared.global [%0], [%1], 16;" :: "r"(dst), "l"(src));
}
__device__ __forceinline__ void cp_commit() {
    asm volatile("cp.async.commit_group;" ::: "memory");
}
template<int N> __device__ __forceinline__ void cp_wait() {
    asm volatile("cp.async.wait_group %0;" :: "n"(N) : "memory");
}

// ------------------------- generic tf32 WMMA GEMM (QKV / out proj) ----------
#define BK  32
#define LDS 40
#define NST 2

template<int MODE>   // MODE: 0 plain store, 1 tf32-rounded
__global__ void __launch_bounds__(256, 2)
wmma_gemm(const float* __restrict__ A, const float* __restrict__ B, float* __restrict__ C,
          int K, int lda, int ldb, int ldc)
{
    constexpr int AELEM = 128 * LDS;
    constexpr int BELEM = 128 * LDS;

    extern __shared__ float sm[];
    float* sA = sm;
    float* sB = sm + (size_t)NST * AELEM;

    const int tid = threadIdx.x;
    const int wid = tid >> 5;
    const int warp_m = wid & 1;
    const int warp_n = wid >> 1;

    const int m0 = blockIdx.y * 128;
    const int n0 = blockIdx.x * 128;
    const int nch = K >> 5;

    wmma::fragment<wmma::accumulator, 16, 16, 8, float> cf[4][2];
    #pragma unroll
    for (int i = 0; i < 4; i++)
        #pragma unroll
        for (int j = 0; j < 2; j++)
            wmma::fill_fragment(cf[i][j], 0.0f);

    auto load = [&](int s, int c) {
        const int k0 = c * BK;
        uint32_t aB = smem_u32(sA + (size_t)s * AELEM);
        uint32_t bB = smem_u32(sB + (size_t)s * BELEM);
        #pragma unroll
        for (int j = 0; j < 4; j++) {
            int f = tid + j * 256, r = f >> 3, q = f & 7;
            cp16(aB + (uint32_t)(r * LDS + q * 4) * 4,
                 A + (size_t)(m0 + r) * lda + k0 + q * 4);
        }
        #pragma unroll
        for (int j = 0; j < 4; j++) {
            int f = tid + j * 256, r = f >> 3, q = f & 7;
            cp16(bB + (uint32_t)(r * LDS + q * 4) * 4,
                 B + (size_t)(n0 + r) * ldb + k0 + q * 4);
        }
        cp_commit();
    };

    load(0, 0);

    for (int c = 0; c < nch; c++) {
        const int s = c & 1;
        cp_wait<0>();
        __syncthreads();
        if (c + 1 < nch) load((c + 1) & 1, c + 1);

        const float* As = sA + (size_t)s * AELEM + warp_m * 64 * LDS;
        const float* Bs = sB + (size_t)s * BELEM + warp_n * 32 * LDS;
        #pragma unroll
        for (int kc = 0; kc < 4; kc++) {
            wmma::fragment<wmma::matrix_a, 16, 16, 8, wmma::precision::tf32, wmma::row_major> af[4];
            wmma::fragment<wmma::matrix_b, 16, 16, 8, wmma::precision::tf32, wmma::col_major> bf[2];
            #pragma unroll
            for (int i = 0; i < 4; i++)
                wmma::load_matrix_sync(af[i], As + i * 16 * LDS + kc * 8, LDS);
            #pragma unroll
            for (int j = 0; j < 2; j++)
                wmma::load_matrix_sync(bf[j], Bs + j * 16 * LDS + kc * 8, LDS);
            #pragma unroll
            for (int i = 0; i < 4; i++)
                #pragma unroll
                for (int j = 0; j < 2; j++)
                    wmma::mma_sync(cf[i][j], af[i], bf[j], cf[i][j]);
        }
        __syncthreads();
    }

    #pragma unroll
    for (int i = 0; i < 4; i++) {
        #pragma unroll
        for (int j = 0; j < 2; j++) {
            if (MODE == 1) {
                #pragma unroll
                for (int e = 0; e < 8; e++) cf[i][j].x[e] = tf32r(cf[i][j].x[e]);
            }
            float* Cp = C + (size_t)(m0 + warp_m * 64 + i * 16) * ldc
                          + n0 + warp_n * 32 + j * 16;
            wmma::store_matrix_sync(Cp, cf[i][j], ldc, wmma::mem_row_major);
        }
    }
}

// ------------------------- streaming scores + exp + row sums -----------------
// CTA owns (z, 64 q rows); streams K in 32 double-buffered 64-row chunks.
// grid (32 qtile, 32 z), 256 threads, 3 CTAs/SM (68 KB smem).
// Every K load overlaps the previous chunk's MMA/exp/store. Q loaded once.
// Row sums accumulated in registers across all 32 chunks -> rowsum[row].
#define SLD 68

__global__ void __launch_bounds__(256, 3)
scores_exp_kernel(const float* __restrict__ QKV, float* __restrict__ E,
                  float* __restrict__ rowsum)
{
    extern __shared__ float sm[];
    float* sQ    = sm;                       // [64][68]
    float* sK[2] = { sm + 64 * SLD, sm + 128 * SLD };  // 2 x [64][68]
    float* sE    = sm + 192 * SLD;           // [64][68] staging

    const int tid = threadIdx.x;
    const int wid = tid >> 5;
    const int z = blockIdx.y, b = z >> 4, h = z & 15;
    const int q0 = blockIdx.x * 64;

    const float* Qb = QKV + (size_t)b * SEQ * QKVLD + h * DK;
    const float* Kb = QKV + (size_t)b * SEQ * QKVLD + D_MODEL + h * DK;
    float* Eb = E + (size_t)z * SEQ * SEQ + (size_t)q0 * SEQ;

    auto loadK = [&](int nt) {
        uint32_t kB = smem_u32(sK[nt & 1]);
        #pragma unroll
        for (int j = 0; j < 4; j++) {
            int f = tid + j * 256, r = f >> 4, c = f & 15;
            cp16(kB + (uint32_t)(r * SLD + c * 4) * 4,
                 Kb + (size_t)(nt * 64 + r) * QKVLD + c * 4);
        }
        cp_commit();
    };

    // prologue: Q + K0 in group 0, K1 in group 1
    {
        uint32_t qB = smem_u32(sQ);
        #pragma unroll
        for (int j = 0; j < 4; j++) {
            int f = tid + j * 256, r = f >> 4, c = f & 15;
            cp16(qB + (uint32_t)(r * SLD + c * 4) * 4,
                 Qb + (size_t)(q0 + r) * QKVLD + c * 4);
        }
    }
    loadK(0);
    loadK(1);

    const int wm = wid & 1, wn = wid >> 1;   // warp tile 32q x 16n
    float rowacc[4] = {0.f, 0.f, 0.f, 0.f};

    for (int nt = 0; nt < 32; nt++) {
        float* bk = sK[nt & 1];
        if (nt < 31) cp_wait<1>(); else cp_wait<0>();
        __syncthreads();   // K(nt) visible; also orders prior sE reads vs new writes

        wmma::fragment<wmma::accumulator, 16, 16, 8, float> acc[2];
        #pragma unroll
        for (int i = 0; i < 2; i++) wmma::fill_fragment(acc[i], 0.f);
        #pragma unroll
        for (int ks = 0; ks < 8; ks++) {
            wmma::fragment<wmma::matrix_b, 16, 16, 8, wmma::precision::tf32, wmma::col_major> bf;
            wmma::load_matrix_sync(bf, bk + (wn * 16) * SLD + ks * 8, SLD);
            #pragma unroll
            for (int i = 0; i < 2; i++) {
                wmma::fragment<wmma::matrix_a, 16, 16, 8, wmma::precision::tf32, wmma::row_major> af;
                wmma::load_matrix_sync(af, sQ + (wm * 32 + i * 16) * SLD + ks * 8, SLD);
                wmma::mma_sync(acc[i], af, bf, acc[i]);
            }
        }
        __syncthreads();   // all MMA reads of bk complete

        if (nt + 2 < 32) loadK(nt + 2);   // prefetch into freed buffer (overlaps below)

        #pragma unroll
        for (int i = 0; i < 2; i++) {
            #pragma unroll
            for (int e = 0; e < 8; e++) acc[i].x[e] = __expf(acc[i].x[e] * 0.125f);
            wmma::store_matrix_sync(sE + (wm * 32 + i * 16) * SLD + wn * 16,
                                    acc[i], SLD, wmma::mem_row_major);
        }
        __syncthreads();   // sE staged

        // coalesced E write + register row-sum accumulation
        float* Ebn = Eb + nt * 64;
        #pragma unroll
        for (int j = 0; j < 4; j++) {
            int f = tid + j * 256, rr = f >> 4, c4 = f & 15;
            float4 v = *reinterpret_cast<const float4*>(sE + rr * SLD + c4 * 4);
            *reinterpret_cast<float4*>(Ebn + (size_t)rr * SEQ + c4 * 4) = v;
            rowacc[j] += (v.x + v.y) + (v.z + v.w);
        }
        // no sync: next iteration's post-wait sync orders sE reuse
    }

    // finalize row sums: 16 consecutive lanes (half-warp) share each row
    #pragma unroll
    for (int j = 0; j < 4; j++) {
        float s = rowacc[j];
        s += __shfl_xor_sync(0xFFFFFFFFu, s, 1);
        s += __shfl_xor_sync(0xFFFFFFFFu, s, 2);
        s += __shfl_xor_sync(0xFFFFFFFFu, s, 4);
        s += __shfl_xor_sync(0xFFFFFFFFu, s, 8);
        if ((tid & 15) == 0)
            rowsum[(size_t)z * SEQ + q0 + (tid >> 4) + j * 16] = s;
    }
}

// ------------------------- normalize (write P) + P@V -------------------------
// 128q x 64kv chunks: grid (16 qtile, 32 z), 256 threads, 2 CTAs/SM.
#define PVLD 68

__global__ void __launch_bounds__(256, 2)
pv_kernel(float* __restrict__ E, const float* __restrict__ QKV,
          const float* __restrict__ rowsum, float* __restrict__ O)
{
    extern __shared__ float sm[];            // sE[2][128][68] + sV[2][64][68]
    __shared__ float sinv[128];
    float* sE[2] = { sm,                  sm + 128 * PVLD };
    float* sV[2] = { sm + 2 * 128 * PVLD, sm + 2 * 128 * PVLD + 64 * PVLD };

    const int tid = threadIdx.x;
    const int wid = tid >> 5;
    const int z = blockIdx.y, b = z >> 4, h = z & 15;
    const int q0 = blockIdx.x * 128;

    float* Eb = E + (size_t)z * SEQ * SEQ + (size_t)q0 * SEQ;
    const float* Vb = QKV + (size_t)b * SEQ * QKVLD + 2 * D_MODEL + h * DK;

    if (tid < 128)
        sinv[tid] = 1.0f / rowsum[(size_t)z * SEQ + q0 + tid];

    auto prefetch = [&](int kt) {
        uint32_t eB = smem_u32(sE[kt & 1]);
        uint32_t vB = smem_u32(sV[kt & 1]);
        #pragma unroll
        for (int j = 0; j < 8; j++) {
            int f = tid + j * 256, r = f >> 4, c4 = f & 15;
            cp16(eB + (uint32_t)(r * PVLD + c4 * 4) * 4,
                 Eb + (size_t)r * SEQ + kt * 64 + c4 * 4);
        }
        #pragma unroll
        for (int j = 0; j < 4; j++) {
            int f = tid + j * 256, r = f >> 4, c4 = f & 15;
            cp16(vB + (uint32_t)(r * PVLD + c4 * 4) * 4,
                 Vb + (size_t)(kt * 64 + r) * QKVLD + c4 * 4);
        }
        cp_commit();
    };
    prefetch(0);
    prefetch(1);

    const int wm = wid & 3, wn = wid >> 2;   // O(128x64): warp tile 32q x 32d
    wmma::fragment<wmma::accumulator, 16, 16, 8, float> acc[2][2];
    #pragma unroll
    for (int i = 0; i < 2; i++)
        #pragma unroll
        for (int j = 0; j < 2; j++)
            wmma::fill_fragment(acc[i][j], 0.f);

    for (int kt = 0; kt < 32; kt++) {
        float* bufE = sE[kt & 1];
        float* bufV = sV[kt & 1];
        if (kt < 31) cp_wait<1>(); else cp_wait<0>();
        __syncthreads();

        // normalize + tf32-round in smem; write final P to gmem (coalesced)
        #pragma unroll
        for (int j = 0; j < 8; j++) {
            int f = tid + j * 256, r = f >> 4, c4 = f & 15;
            float4* sp = reinterpret_cast<float4*>(bufE + r * PVLD + c4 * 4);
            float4 v = *sp;
            const float iv = sinv[r];
            v.x = tf32r(v.x * iv); v.y = tf32r(v.y * iv);
            v.z = tf32r(v.z * iv); v.w = tf32r(v.w * iv);
            *sp = v;
            *reinterpret_cast<float4*>(Eb + (size_t)r * SEQ + kt * 64 + c4 * 4) = v;
        }
        __syncthreads();

        // O += P_chunk @ V_chunk (both operands from smem)
        #pragma unroll
        for (int ks = 0; ks < 8; ks++) {
            wmma::fragment<wmma::matrix_b, 16, 16, 8, wmma::precision::tf32, wmma::row_major> bf[2];
            #pragma unroll
            for (int j = 0; j < 2; j++)
                wmma::load_matrix_sync(bf[j], bufV + (ks * 8) * PVLD + wn * 32 + j * 16, PVLD);
            #pragma unroll
            for (int i = 0; i < 2; i++) {
                wmma::fragment<wmma::matrix_a, 16, 16, 8, wmma::precision::tf32, wmma::row_major> af;
                wmma::load_matrix_sync(af, bufE + (wm * 32 + i * 16) * PVLD + ks * 8, PVLD);
                #pragma unroll
                for (int j = 0; j < 2; j++)
                    wmma::mma_sync(acc[i][j], af, bf[j], acc[i][j]);
            }
        }
        __syncthreads();
        if (kt + 2 < 32) prefetch(kt + 2);
    }

    #pragma unroll
    for (int i = 0; i < 2; i++)
        #pragma unroll
        for (int j = 0; j < 2; j++) {
            #pragma unroll
            for (int e = 0; e < 8; e++) acc[i][j].x[e] = tf32r(acc[i][j].x[e]);
            float* Op = O + (size_t)(b * SEQ + q0 + wm * 32 + i * 16) * D_MODEL
                          + h * DK + wn * 32 + j * 16;
            wmma::store_matrix_sync(Op, acc[i][j], D_MODEL, wmma::mem_row_major);
        }
}

// ------------------------- cvt kernels ---------------------------------------
__global__ void cvt_x_kernel(const float4* __restrict__ src, float4* __restrict__ dst, int n4)
{
    int i = blockIdx.x * blockDim.x + threadIdx.x;
    if (i < n4) {
        float4 v = src[i];
        v.x = tf32r(v.x); v.y = tf32r(v.y); v.z = tf32r(v.z); v.w = tf32r(v.w);
        dst[i] = v;
    }
}
__global__ void cvt_w_kernel(const float4* __restrict__ w0, const float4* __restrict__ w1,
                             const float4* __restrict__ w2, const float4* __restrict__ w3,
                             float4* __restrict__ dst)
{
    const int per = D_MODEL * D_MODEL / 4;
    int i = blockIdx.x * blockDim.x + threadIdx.x;
    const float4* src = (i < per) ? w0 : (i < 2 * per) ? w1 : (i < 3 * per) ? w2 : w3;
    float4 v = src[i & (per - 1)];
    v.x = tf32r(v.x); v.y = tf32r(v.y); v.z = tf32r(v.z); v.w = tf32r(v.w);
    dst[i] = v;
}

// ------------------------- host ----------------------------------------------
extern "C" void kernel_launch(void* const* d_in, const int* in_sizes, int n_in,
                              void* d_out, int out_size)
{
    const float* x  = (const float*)d_in[0];
    const float* Wq = (const float*)d_in[1];
    const float* Wk = (const float*)d_in[2];
    const float* Wv = (const float*)d_in[3];
    const float* Wo = (const float*)d_in[4];
    float* out = (float*)d_out;

    float *pxt, *pwt, *pQKV, *pO, *prs;
    cudaGetSymbolAddress((void**)&pxt,  g_xt);
    cudaGetSymbolAddress((void**)&pwt,  g_wt);
    cudaGetSymbolAddress((void**)&pQKV, g_QKV);
    cudaGetSymbolAddress((void**)&pO,   g_O);
    cudaGetSymbolAddress((void**)&prs,  g_rowsum);

    const size_t projN = (size_t)MTOT * D_MODEL;
    float* S = out + projN;   // attn_weights region (E -> P in place)
    const size_t M2 = (size_t)D_MODEL * D_MODEL;

    const int smemG  = NST * (128 + 128) * LDS * 4;          //  81920 (proj GEMMs)
    const int smemSC = 256 * SLD * 4;                        //  69632 (scores: Q+2K+E)
    const int smemPV = (2 * 128 + 2 * 64) * PVLD * 4;        // 104448 (pv)
    cudaFuncSetAttribute(wmma_gemm<1>,      cudaFuncAttributeMaxDynamicSharedMemorySize, smemG);
    cudaFuncSetAttribute(wmma_gemm<0>,      cudaFuncAttributeMaxDynamicSharedMemorySize, smemG);
    cudaFuncSetAttribute(scores_exp_kernel, cudaFuncAttributeMaxDynamicSharedMemorySize, smemSC);
    cudaFuncSetAttribute(pv_kernel,         cudaFuncAttributeMaxDynamicSharedMemorySize, smemPV);

    // 1) tf32-round inputs
    cvt_x_kernel<<<(int)(projN / 4 / 256), 256>>>((const float4*)x, (float4*)pxt, (int)(projN / 4));
    cvt_w_kernel<<<(int)(4 * M2 / 4 / 256), 256>>>((const float4*)Wq, (const float4*)Wk,
                                                   (const float4*)Wv, (const float4*)Wo, (float4*)pwt);

    // 2) fused QKV projection (tf32-rounded store)
    dim3 gqkv(QKVLD / 128, MTOT / 128);
    wmma_gemm<1><<<gqkv, 256, smemG>>>(pxt, pwt, pQKV, D_MODEL, D_MODEL, D_MODEL, QKVLD);

    // 3) streaming scores: E = exp(QK^T/8), full row sums in one pass
    scores_exp_kernel<<<dim3(SEQ / 64, BATCH * N_HEADS), 256, smemSC>>>(pQKV, S, prs);

    // 4) normalize (write P in place) + O = P @ V (128q x 64kv chunks)
    pv_kernel<<<dim3(SEQ / 128, BATCH * N_HEADS), 256, smemPV>>>(S, pQKV, prs, pO);

    // 5) out = O @ Wo^T
    dim3 gproj(D_MODEL / 128, MTOT / 128);
    wmma_gemm<0><<<gproj, 256, smemG>>>(pO, pwt + 3 * M2, out, D_MODEL, D_MODEL, D_MODEL, D_MODEL);
}